// round 3
// baseline (speedup 1.0000x reference)
#include <cuda_runtime.h>
#include <cuda_bf16.h>
#include <math.h>
#include <cstdint>

// Problem constants
#define NN    50000
#define EE    800000
#define ET    (EE + NN)      // edges + self loops
#define FIN   128
#define HIDC  128
#define HEADS 4
#define GG    512
#define C1    (HEADS * HIDC) // 512

// ---------------- scratch (static device globals; no allocation allowed) ---
__device__ float g_h1[(size_t)NN * C1];      // x @ W1
__device__ float g_act1[(size_t)NN * C1];    // elu(agg1 + b1)
__device__ float g_h2[(size_t)NN * HIDC];    // act1 @ W2
__device__ float g_out2[(size_t)NN * HIDC];  // elu(agg2 + b2)
__device__ float g_asrc1[NN * HEADS];
__device__ float g_adst1[NN * HEADS];
__device__ float g_asrc2[NN];
__device__ float g_adst2[NN];
__device__ int   g_deg[NN];
__device__ int   g_rowptr[NN + 1];
__device__ int   g_cursor[NN];
__device__ int   g_esrc[ET];
__device__ float g_pool[GG * HIDC];
__device__ float g_cnt[GG];

// ====================== bf16 mma.sync GEMM =================================
// C[M,Nn] = A[M,K] @ B[K,Nn], fp32 in/out, bf16 hi/lo split (3 MMAs/product).
// Block tile 128x128, 8 warps (each 32x64), K-chunk 32.
// SMEM: A as [row][k] stride 40 halves; B transposed as [n][k] stride 40.

#define KC     32
#define APAD   40

__device__ __forceinline__ void mma16816(float* c, const uint32_t* a, const uint32_t* b) {
    asm volatile(
        "mma.sync.aligned.m16n8k16.row.col.f32.bf16.bf16.f32 "
        "{%0,%1,%2,%3}, {%4,%5,%6,%7}, {%8,%9}, {%0,%1,%2,%3};"
        : "+f"(c[0]), "+f"(c[1]), "+f"(c[2]), "+f"(c[3])
        : "r"(a[0]), "r"(a[1]), "r"(a[2]), "r"(a[3]), "r"(b[0]), "r"(b[1]));
}

__device__ __forceinline__ uint32_t pack_hi2(float x, float y) {
    __nv_bfloat162 t = __floats2bfloat162_rn(x, y);
    return *reinterpret_cast<uint32_t*>(&t);
}

__global__ __launch_bounds__(256) void mma_gemm_kernel(
    const float* __restrict__ A, const float* __restrict__ B,
    float* __restrict__ C, int M, int Nn, int K)
{
    __shared__ unsigned short Ah[128 * APAD];
    __shared__ unsigned short Al[128 * APAD];
    __shared__ unsigned short Bh[128 * APAD];
    __shared__ unsigned short Bl[128 * APAD];

    int tid = threadIdx.x;
    int wid = tid >> 5, lane = tid & 31;
    int warp_m = wid & 3;            // 4 warps over M: 32 rows each
    int warp_n = wid >> 2;           // 2 warps over N: 64 cols each
    int g = lane >> 2, tg = lane & 3;
    int rowBase = blockIdx.y * 128;
    int colBase = blockIdx.x * 128;

    float acc[2][8][4];
#pragma unroll
    for (int mt = 0; mt < 2; mt++)
#pragma unroll
        for (int nt = 0; nt < 8; nt++)
#pragma unroll
            for (int j = 0; j < 4; j++) acc[mt][nt][j] = 0.f;

    for (int k0 = 0; k0 < K; k0 += KC) {
        // ---- load A tile: 128 rows x 32 k (hi/lo) ----
#pragma unroll
        for (int l = 0; l < 4; l++) {
            int idx = tid + l * 256;          // 0..1023
            int row = idx >> 3;
            int q = idx & 7;                  // float4 within 32 k
            int gr = rowBase + row;
            float4 v = make_float4(0.f, 0.f, 0.f, 0.f);
            if (gr < M) v = *reinterpret_cast<const float4*>(&A[(size_t)gr * K + k0 + q * 4]);
            __nv_bfloat16 h0 = __float2bfloat16_rn(v.x), h1 = __float2bfloat16_rn(v.y);
            __nv_bfloat16 h2 = __float2bfloat16_rn(v.z), h3 = __float2bfloat16_rn(v.w);
            float r0 = v.x - __bfloat162float(h0), r1 = v.y - __bfloat162float(h1);
            float r2 = v.z - __bfloat162float(h2), r3 = v.w - __bfloat162float(h3);
            int so = row * APAD + q * 4;
            uint2 hh = make_uint2(
                ((uint32_t)__bfloat16_as_ushort(h0)) | ((uint32_t)__bfloat16_as_ushort(h1) << 16),
                ((uint32_t)__bfloat16_as_ushort(h2)) | ((uint32_t)__bfloat16_as_ushort(h3) << 16));
            *reinterpret_cast<uint2*>(&Ah[so]) = hh;
            *reinterpret_cast<uint2*>(&Al[so]) = make_uint2(pack_hi2(r0, r1), pack_hi2(r2, r3));
        }
        // ---- load B tile transposed: Bs[n][kk] = B[k0+kk][colBase+n] ----
#pragma unroll
        for (int l = 0; l < 4; l++) {
            int idx = tid + l * 256;
            int kk = idx >> 5;                // 0..31
            int q = idx & 31;                 // float4 over 128 n
            float4 v = *reinterpret_cast<const float4*>(&B[(size_t)(k0 + kk) * Nn + colBase + q * 4]);
            float vv[4] = {v.x, v.y, v.z, v.w};
#pragma unroll
            for (int j = 0; j < 4; j++) {
                int n = q * 4 + j;
                __nv_bfloat16 h = __float2bfloat16_rn(vv[j]);
                __nv_bfloat16 lo = __float2bfloat16_rn(vv[j] - __bfloat162float(h));
                Bh[n * APAD + kk] = __bfloat16_as_ushort(h);
                Bl[n * APAD + kk] = __bfloat16_as_ushort(lo);
            }
        }
        __syncthreads();

        // ---- MMAs over the 2 k16 steps ----
#pragma unroll
        for (int ks = 0; ks < 2; ks++) {
            int kk = ks * 16;
            uint32_t afh[2][4], afl[2][4];
#pragma unroll
            for (int mt = 0; mt < 2; mt++) {
                int r0 = (warp_m * 32 + mt * 16 + g) * APAD + kk + tg * 2;
                int r8 = r0 + 8 * APAD;
                afh[mt][0] = *reinterpret_cast<uint32_t*>(&Ah[r0]);
                afh[mt][1] = *reinterpret_cast<uint32_t*>(&Ah[r8]);
                afh[mt][2] = *reinterpret_cast<uint32_t*>(&Ah[r0 + 8]);
                afh[mt][3] = *reinterpret_cast<uint32_t*>(&Ah[r8 + 8]);
                afl[mt][0] = *reinterpret_cast<uint32_t*>(&Al[r0]);
                afl[mt][1] = *reinterpret_cast<uint32_t*>(&Al[r8]);
                afl[mt][2] = *reinterpret_cast<uint32_t*>(&Al[r0 + 8]);
                afl[mt][3] = *reinterpret_cast<uint32_t*>(&Al[r8 + 8]);
            }
#pragma unroll
            for (int nt = 0; nt < 8; nt++) {
                int nb = (warp_n * 64 + nt * 8 + g) * APAD + kk + tg * 2;
                uint32_t bfh[2], bfl[2];
                bfh[0] = *reinterpret_cast<uint32_t*>(&Bh[nb]);
                bfh[1] = *reinterpret_cast<uint32_t*>(&Bh[nb + 8]);
                bfl[0] = *reinterpret_cast<uint32_t*>(&Bl[nb]);
                bfl[1] = *reinterpret_cast<uint32_t*>(&Bl[nb + 8]);
#pragma unroll
                for (int mt = 0; mt < 2; mt++) {
                    mma16816(acc[mt][nt], afh[mt], bfh);
                    mma16816(acc[mt][nt], afh[mt], bfl);
                    mma16816(acc[mt][nt], afl[mt], bfh);
                }
            }
        }
        __syncthreads();
    }

    // ---- epilogue ----
#pragma unroll
    for (int mt = 0; mt < 2; mt++) {
        int r0 = rowBase + warp_m * 32 + mt * 16 + g;
#pragma unroll
        for (int nt = 0; nt < 8; nt++) {
            int col = colBase + warp_n * 64 + nt * 8 + tg * 2;
            if (r0 < M)
                *reinterpret_cast<float2*>(&C[(size_t)r0 * Nn + col]) =
                    make_float2(acc[mt][nt][0], acc[mt][nt][1]);
            if (r0 + 8 < M)
                *reinterpret_cast<float2*>(&C[(size_t)(r0 + 8) * Nn + col]) =
                    make_float2(acc[mt][nt][2], acc[mt][nt][3]);
        }
    }
}

// ---------------- init ------------------------------------------------------
__global__ void init_kernel() {
    int i = blockIdx.x * blockDim.x + threadIdx.x;
    int stride = gridDim.x * blockDim.x;
    for (int k = i; k < NN; k += stride) { g_deg[k] = 1; g_cursor[k] = 0; }
    for (int k = i; k < GG * HIDC; k += stride) g_pool[k] = 0.f;
    for (int k = i; k < GG; k += stride) g_cnt[k] = 0.f;
}

// ---------------- degree count ---------------------------------------------
__global__ void count_kernel(const int* __restrict__ ei) {
    int i = blockIdx.x * blockDim.x + threadIdx.x;
    if (i < EE) atomicAdd(&g_deg[ei[EE + i]], 1);
}

// ---------------- exclusive scan (single block) ----------------------------
__global__ void scan_kernel() {
    __shared__ int sm[1024];
    __shared__ int carry_s;
    int tid = threadIdx.x;
    if (tid == 0) carry_s = 0;
    __syncthreads();
    for (int base = 0; base < NN; base += 1024) {
        int carry = carry_s;
        int i = base + tid;
        int v = (i < NN) ? g_deg[i] : 0;
        sm[tid] = v;
        __syncthreads();
        for (int off = 1; off < 1024; off <<= 1) {
            int t = (tid >= off) ? sm[tid - off] : 0;
            __syncthreads();
            sm[tid] += t;
            __syncthreads();
        }
        if (i < NN) g_rowptr[i] = carry + sm[tid] - v;
        if (tid == 1023) carry_s = carry + sm[1023];
        __syncthreads();
    }
    if (tid == 0) g_rowptr[NN] = carry_s;
}

// ---------------- scatter into CSR (edges + self loops) --------------------
__global__ void scatter_kernel(const int* __restrict__ ei) {
    int i = blockIdx.x * blockDim.x + threadIdx.x;
    if (i < EE) {
        int s = ei[i];
        int d = ei[EE + i];
        int pos = g_rowptr[d] + atomicAdd(&g_cursor[d], 1);
        g_esrc[pos] = s;
    } else if (i < ET) {
        int n = i - EE;
        int pos = g_rowptr[n] + atomicAdd(&g_cursor[n], 1);
        g_esrc[pos] = n;
    }
}

// ---------------- attention dot products (asrc/adst per node,head) ---------
template <int H, int C>
__global__ void dots_kernel(const float* __restrict__ h,
                            const float* __restrict__ a_src,
                            const float* __restrict__ a_dst,
                            float* __restrict__ asrc, float* __restrict__ adst)
{
    int node = blockIdx.x;
    int w = threadIdx.x / 32, lane = threadIdx.x % 32;
    const float* hp = h + (size_t)node * H * C + w * C;
    float s1 = 0.f, s2 = 0.f;
#pragma unroll
    for (int i = lane; i < C; i += 32) {
        float v = hp[i];
        s1 += v * a_src[w * C + i];
        s2 += v * a_dst[w * C + i];
    }
#pragma unroll
    for (int off = 16; off; off >>= 1) {
        s1 += __shfl_down_sync(0xffffffffu, s1, off);
        s2 += __shfl_down_sync(0xffffffffu, s2, off);
    }
    if (lane == 0) {
        asrc[node * H + w] = s1;
        adst[node * H + w] = s2;
    }
}

// ---------------- block reductions (128 threads) ---------------------------
__device__ __forceinline__ float blockReduceMax128(float v, float* s) {
    int t = threadIdx.x;
    __syncthreads();
    s[t] = v;
    __syncthreads();
    if (t < 64) s[t] = fmaxf(s[t], s[t + 64]);
    __syncthreads();
    if (t < 32) {
        float x = fmaxf(s[t], s[t + 32]);
#pragma unroll
        for (int o = 16; o; o >>= 1) x = fmaxf(x, __shfl_down_sync(0xffffffffu, x, o));
        if (t == 0) s[0] = x;
    }
    __syncthreads();
    float r = s[0];
    __syncthreads();
    return r;
}

__device__ __forceinline__ float blockReduceSum128(float v, float* s) {
    int t = threadIdx.x;
    __syncthreads();
    s[t] = v;
    __syncthreads();
    if (t < 64) s[t] += s[t + 64];
    __syncthreads();
    if (t < 32) {
        float x = s[t] + s[t + 32];
#pragma unroll
        for (int o = 16; o; o >>= 1) x += __shfl_down_sync(0xffffffffu, x, o);
        if (t == 0) s[0] = x;
    }
    __syncthreads();
    float r = s[0];
    __syncthreads();
    return r;
}

// ---------------- fused attention + aggregation per dst node ---------------
template <int H, int C>
__global__ __launch_bounds__(C) void agg_kernel(
    const float* __restrict__ h,
    const float* __restrict__ asrc, const float* __restrict__ adst,
    const float* __restrict__ bias, float* __restrict__ out)
{
    const int CH = 1024;
    __shared__ int   s_src[CH];
    __shared__ float s_w[CH * H];
    __shared__ float s_red[C];

    int node = blockIdx.x, t = threadIdx.x;
    int beg = g_rowptr[node], end = g_rowptr[node + 1];

    float ad[H], m[H], ssum[H], acc[H];
#pragma unroll
    for (int hh = 0; hh < H; hh++) {
        ad[hh] = adst[node * H + hh];
        m[hh] = -1e30f;
        ssum[hh] = 0.f;
        acc[hh] = 0.f;
    }

    for (int cbeg = beg; cbeg < end; cbeg += CH) {
        int clen = min(CH, end - cbeg);
        float lmax[H];
#pragma unroll
        for (int hh = 0; hh < H; hh++) lmax[hh] = -1e30f;
        for (int i = t; i < clen; i += C) {
            int s = g_esrc[cbeg + i];
            s_src[i] = s;
#pragma unroll
            for (int hh = 0; hh < H; hh++) {
                float l = asrc[s * H + hh] + ad[hh];
                l = l > 0.f ? l : 0.2f * l;
                s_w[i * H + hh] = l;
                lmax[hh] = fmaxf(lmax[hh], l);
            }
        }
        float newm[H], f[H];
#pragma unroll
        for (int hh = 0; hh < H; hh++) {
            float cm = blockReduceMax128(lmax[hh], s_red);
            newm[hh] = fmaxf(m[hh], cm);
            f[hh] = __expf(m[hh] - newm[hh]);
            m[hh] = newm[hh];
        }
        float ls[H];
#pragma unroll
        for (int hh = 0; hh < H; hh++) ls[hh] = 0.f;
        for (int i = t; i < clen; i += C) {
#pragma unroll
            for (int hh = 0; hh < H; hh++) {
                float w = __expf(s_w[i * H + hh] - m[hh]);
                s_w[i * H + hh] = w;
                ls[hh] += w;
            }
        }
#pragma unroll
        for (int hh = 0; hh < H; hh++) {
            float cs = blockReduceSum128(ls[hh], s_red);
            ssum[hh] = ssum[hh] * f[hh] + cs;
            acc[hh] *= f[hh];
        }
#pragma unroll 2
        for (int i = 0; i < clen; i++) {
            int s = s_src[i];
            const float* hp = h + (size_t)s * (H * C);
#pragma unroll
            for (int hh = 0; hh < H; hh++) {
                acc[hh] += s_w[i * H + hh] * hp[hh * C + t];
            }
        }
        __syncthreads();
    }
#pragma unroll
    for (int hh = 0; hh < H; hh++) {
        float v = acc[hh] / ssum[hh] + bias[hh * C + t];
        out[(size_t)node * H * C + hh * C + t] = v > 0.f ? v : expm1f(v);
    }
}

// ---------------- pooling ---------------------------------------------------
__global__ void pool_kernel(const int* __restrict__ batch) {
    int i = blockIdx.x * blockDim.x + threadIdx.x;
    if (i < NN * HIDC) {
        int node = i >> 7, c = i & 127;
        int g = batch[node];
        atomicAdd(&g_pool[g * HIDC + c], g_out2[i]);
        if (c == 0) atomicAdd(&g_cnt[g], 1.0f);
    }
}

__global__ void final_kernel(const float* __restrict__ Wl,
                             const float* __restrict__ bl,
                             float* __restrict__ out)
{
    __shared__ float s_red[128];
    int g = blockIdx.x, t = threadIdx.x;
    float c = fmaxf(g_cnt[g], 1.0f);
    float v = g_pool[g * HIDC + t] / c * Wl[t];
    float r = blockReduceSum128(v, s_red);
    if (t == 0) out[g] = r + bl[0];
}

// ---------------- launch ----------------------------------------------------
extern "C" void kernel_launch(void* const* d_in, const int* in_sizes, int n_in,
                              void* d_out, int out_size)
{
    const float* x       = (const float*)d_in[0];
    const int*   ei      = (const int*)  d_in[1];
    const int*   batch   = (const int*)  d_in[2];
    const float* W1      = (const float*)d_in[3];
    const float* a_src1  = (const float*)d_in[4];
    const float* a_dst1  = (const float*)d_in[5];
    const float* b1      = (const float*)d_in[6];
    const float* W2      = (const float*)d_in[7];
    const float* a_src2  = (const float*)d_in[8];
    const float* a_dst2  = (const float*)d_in[9];
    const float* b2      = (const float*)d_in[10];
    const float* Wl      = (const float*)d_in[11];
    const float* bl      = (const float*)d_in[12];
    float* out = (float*)d_out;

    float *p_h1, *p_act1, *p_h2, *p_out2, *p_asrc1, *p_adst1, *p_asrc2, *p_adst2;
    cudaGetSymbolAddress((void**)&p_h1,    g_h1);
    cudaGetSymbolAddress((void**)&p_act1,  g_act1);
    cudaGetSymbolAddress((void**)&p_h2,    g_h2);
    cudaGetSymbolAddress((void**)&p_out2,  g_out2);
    cudaGetSymbolAddress((void**)&p_asrc1, g_asrc1);
    cudaGetSymbolAddress((void**)&p_adst1, g_adst1);
    cudaGetSymbolAddress((void**)&p_asrc2, g_asrc2);
    cudaGetSymbolAddress((void**)&p_adst2, g_adst2);

    // build CSR (counting sort by dst, self loops included)
    init_kernel<<<512, 256>>>();
    count_kernel<<<(EE + 255) / 256, 256>>>(ei);
    scan_kernel<<<1, 1024>>>();
    scatter_kernel<<<(ET + 255) / 256, 256>>>(ei);

    // layer 1: h1 = x @ W1 (bf16-split tensor-core GEMM)
    {
        dim3 grid(C1 / 128, (NN + 127) / 128);
        mma_gemm_kernel<<<grid, 256>>>(x, W1, p_h1, NN, C1, FIN);
    }
    dots_kernel<HEADS, HIDC><<<NN, 32 * HEADS>>>(p_h1, a_src1, a_dst1, p_asrc1, p_adst1);
    agg_kernel<HEADS, HIDC><<<NN, HIDC>>>(p_h1, p_asrc1, p_adst1, b1, p_act1);

    // layer 2: h2 = act1 @ W2
    {
        dim3 grid(HIDC / 128, (NN + 127) / 128);
        mma_gemm_kernel<<<grid, 256>>>(p_act1, W2, p_h2, NN, HIDC, C1);
    }
    dots_kernel<1, HIDC><<<NN, 32>>>(p_h2, a_src2, a_dst2, p_asrc2, p_adst2);
    agg_kernel<1, HIDC><<<NN, HIDC>>>(p_h2, p_asrc2, p_adst2, b2, p_out2);

    // pooling + linear head
    pool_kernel<<<((size_t)NN * HIDC + 255) / 256, 256>>>(batch);
    final_kernel<<<GG, HIDC>>>(Wl, bl, out);
}

// round 5
// speedup vs baseline: 1.6937x; 1.6937x over previous
#include <cuda_runtime.h>
#include <cuda_bf16.h>
#include <math.h>
#include <cstdint>

// Problem constants
#define NN    50000
#define EE    800000
#define ET    (EE + NN)      // edges + self loops
#define FIN   128
#define HIDC  128
#define HEADS 4
#define GG    512
#define C1    (HEADS * HIDC) // 512

// ---------------- scratch (static device globals; no allocation allowed) ---
__device__ float g_h1[(size_t)NN * C1];      // x @ W1 (fp32, for dots/gather)
__device__ float g_h2[(size_t)NN * HIDC];    // act1 @ W2
__device__ float g_out2[(size_t)NN * HIDC];  // elu(agg2 + b2)
__device__ __nv_bfloat16 g_xh[(size_t)NN * FIN];   // x hi
__device__ __nv_bfloat16 g_xl[(size_t)NN * FIN];   // x lo
__device__ __nv_bfloat16 g_a1h[(size_t)NN * C1];   // act1 hi
__device__ __nv_bfloat16 g_a1l[(size_t)NN * C1];   // act1 lo
__device__ __nv_bfloat16 g_w1h[C1 * FIN];    // W1^T [512][128] hi
__device__ __nv_bfloat16 g_w1l[C1 * FIN];
__device__ __nv_bfloat16 g_w2h[HIDC * C1];   // W2^T [128][512] hi
__device__ __nv_bfloat16 g_w2l[HIDC * C1];
__device__ float g_asrc1[NN * HEADS];
__device__ float g_adst1[NN * HEADS];
__device__ float g_asrc2[NN];
__device__ float g_adst2[NN];
__device__ int   g_deg[NN];
__device__ int   g_rowptr[NN + 1];
__device__ int   g_cursor[NN];
__device__ int   g_esrc[ET];
__device__ float g_pool[GG * HIDC];
__device__ float g_cnt[GG];

// ====================== conversion kernels =================================
__device__ __forceinline__ void split_bf16(float v, __nv_bfloat16& h, __nv_bfloat16& l) {
    h = __float2bfloat16_rn(v);
    l = __float2bfloat16_rn(v - __bfloat162float(h));
}

__global__ void convert_x_kernel(const float* __restrict__ X, int total) {
    int i = (blockIdx.x * blockDim.x + threadIdx.x) * 4;
    if (i < total) {
        float4 v = *reinterpret_cast<const float4*>(&X[i]);
        __nv_bfloat16 h[4], l[4];
        split_bf16(v.x, h[0], l[0]); split_bf16(v.y, h[1], l[1]);
        split_bf16(v.z, h[2], l[2]); split_bf16(v.w, h[3], l[3]);
        *reinterpret_cast<uint2*>(&g_xh[i]) = *reinterpret_cast<uint2*>(h);
        *reinterpret_cast<uint2*>(&g_xl[i]) = *reinterpret_cast<uint2*>(l);
    }
}

// W [K][Nn] row-major -> Wt [Nn][K] bf16 hi/lo (transposed)
__global__ void convert_w_kernel(const float* __restrict__ W,
                                 __nv_bfloat16* __restrict__ Wth,
                                 __nv_bfloat16* __restrict__ Wtl,
                                 int K, int Nn) {
    int i = blockIdx.x * blockDim.x + threadIdx.x;
    if (i < K * Nn) {
        int k = i / Nn, n = i % Nn;
        __nv_bfloat16 h, l;
        split_bf16(W[i], h, l);
        Wth[n * K + k] = h;
        Wtl[n * K + k] = l;
    }
}

// ====================== bf16 mma.sync GEMM =================================
// C[M,Nn] = A[M,K] @ B[K,Nn]; A,B pre-split bf16 (B pre-transposed [n][k]).
// 3 accumulating MMAs per product: Ah*Bh + Ah*Bl + Al*Bh.
// Block tile 128x128, 8 warps (each 32x64), K-chunk 32.
#define KC     32
#define APAD   40

__device__ __forceinline__ void mma16816(float* c, const uint32_t* a, const uint32_t* b) {
    asm volatile(
        "mma.sync.aligned.m16n8k16.row.col.f32.bf16.bf16.f32 "
        "{%0,%1,%2,%3}, {%4,%5,%6,%7}, {%8,%9}, {%0,%1,%2,%3};"
        : "+f"(c[0]), "+f"(c[1]), "+f"(c[2]), "+f"(c[3])
        : "r"(a[0]), "r"(a[1]), "r"(a[2]), "r"(a[3]), "r"(b[0]), "r"(b[1]));
}

__global__ __launch_bounds__(256) void mma_gemm_kernel(
    const __nv_bfloat16* __restrict__ Ah, const __nv_bfloat16* __restrict__ Al,
    const __nv_bfloat16* __restrict__ Bth, const __nv_bfloat16* __restrict__ Btl,
    float* __restrict__ C, int M, int Nn, int K)
{
    __shared__ unsigned short Ahs[128 * APAD];
    __shared__ unsigned short Als[128 * APAD];
    __shared__ unsigned short Bhs[128 * APAD];
    __shared__ unsigned short Bls[128 * APAD];

    int tid = threadIdx.x;
    int wid = tid >> 5, lane = tid & 31;
    int warp_m = wid & 3;            // 4 warps over M: 32 rows each
    int warp_n = wid >> 2;           // 2 warps over N: 64 cols each
    int g = lane >> 2, tg = lane & 3;
    int rowBase = blockIdx.y * 128;
    int colBase = blockIdx.x * 128;

    float acc[2][8][4];
#pragma unroll
    for (int mt = 0; mt < 2; mt++)
#pragma unroll
        for (int nt = 0; nt < 8; nt++)
#pragma unroll
            for (int j = 0; j < 4; j++) acc[mt][nt][j] = 0.f;

    for (int k0 = 0; k0 < K; k0 += KC) {
        // ---- copy A tile: 128 rows x 32 k, hi/lo (uint2 = 4 halves) ----
#pragma unroll
        for (int l = 0; l < 4; l++) {
            int idx = tid + l * 256;          // 0..1023
            int row = idx >> 3;
            int q = idx & 7;
            int gr = rowBase + row;
            uint2 vh = make_uint2(0u, 0u), vl = make_uint2(0u, 0u);
            if (gr < M) {
                vh = *reinterpret_cast<const uint2*>(&Ah[(size_t)gr * K + k0 + q * 4]);
                vl = *reinterpret_cast<const uint2*>(&Al[(size_t)gr * K + k0 + q * 4]);
            }
            *reinterpret_cast<uint2*>(&Ahs[row * APAD + q * 4]) = vh;
            *reinterpret_cast<uint2*>(&Als[row * APAD + q * 4]) = vl;
        }
        // ---- copy B tile: 128 n-rows x 32 k ----
#pragma unroll
        for (int l = 0; l < 4; l++) {
            int idx = tid + l * 256;
            int n = idx >> 3;
            int q = idx & 7;
            uint2 vh = *reinterpret_cast<const uint2*>(&Bth[(size_t)(colBase + n) * K + k0 + q * 4]);
            uint2 vl = *reinterpret_cast<const uint2*>(&Btl[(size_t)(colBase + n) * K + k0 + q * 4]);
            *reinterpret_cast<uint2*>(&Bhs[n * APAD + q * 4]) = vh;
            *reinterpret_cast<uint2*>(&Bls[n * APAD + q * 4]) = vl;
        }
        __syncthreads();

        // ---- MMAs over the 2 k16 steps ----
#pragma unroll
        for (int ks = 0; ks < 2; ks++) {
            int kk = ks * 16;
            uint32_t afh[2][4], afl[2][4];
#pragma unroll
            for (int mt = 0; mt < 2; mt++) {
                int r0 = (warp_m * 32 + mt * 16 + g) * APAD + kk + tg * 2;
                int r8 = r0 + 8 * APAD;
                afh[mt][0] = *reinterpret_cast<uint32_t*>(&Ahs[r0]);
                afh[mt][1] = *reinterpret_cast<uint32_t*>(&Ahs[r8]);
                afh[mt][2] = *reinterpret_cast<uint32_t*>(&Ahs[r0 + 8]);
                afh[mt][3] = *reinterpret_cast<uint32_t*>(&Ahs[r8 + 8]);
                afl[mt][0] = *reinterpret_cast<uint32_t*>(&Als[r0]);
                afl[mt][1] = *reinterpret_cast<uint32_t*>(&Als[r8]);
                afl[mt][2] = *reinterpret_cast<uint32_t*>(&Als[r0 + 8]);
                afl[mt][3] = *reinterpret_cast<uint32_t*>(&Als[r8 + 8]);
            }
#pragma unroll
            for (int nt = 0; nt < 8; nt++) {
                int nb = (warp_n * 64 + nt * 8 + g) * APAD + kk + tg * 2;
                uint32_t bfh[2], bfl[2];
                bfh[0] = *reinterpret_cast<uint32_t*>(&Bhs[nb]);
                bfh[1] = *reinterpret_cast<uint32_t*>(&Bhs[nb + 8]);
                bfl[0] = *reinterpret_cast<uint32_t*>(&Bls[nb]);
                bfl[1] = *reinterpret_cast<uint32_t*>(&Bls[nb + 8]);
#pragma unroll
                for (int mt = 0; mt < 2; mt++) {
                    mma16816(acc[mt][nt], afh[mt], bfh);
                    mma16816(acc[mt][nt], afh[mt], bfl);
                    mma16816(acc[mt][nt], afl[mt], bfh);
                }
            }
        }
        __syncthreads();
    }

    // ---- epilogue ----
#pragma unroll
    for (int mt = 0; mt < 2; mt++) {
        int r0 = rowBase + warp_m * 32 + mt * 16 + g;
#pragma unroll
        for (int nt = 0; nt < 8; nt++) {
            int col = colBase + warp_n * 64 + nt * 8 + tg * 2;
            if (r0 < M)
                *reinterpret_cast<float2*>(&C[(size_t)r0 * Nn + col]) =
                    make_float2(acc[mt][nt][0], acc[mt][nt][1]);
            if (r0 + 8 < M)
                *reinterpret_cast<float2*>(&C[(size_t)(r0 + 8) * Nn + col]) =
                    make_float2(acc[mt][nt][2], acc[mt][nt][3]);
        }
    }
}

// ---------------- init ------------------------------------------------------
__global__ void init_kernel() {
    int i = blockIdx.x * blockDim.x + threadIdx.x;
    int stride = gridDim.x * blockDim.x;
    for (int k = i; k < NN; k += stride) { g_deg[k] = 1; g_cursor[k] = 0; }
    for (int k = i; k < GG * HIDC; k += stride) g_pool[k] = 0.f;
    for (int k = i; k < GG; k += stride) g_cnt[k] = 0.f;
}

// ---------------- degree count ---------------------------------------------
__global__ void count_kernel(const int* __restrict__ ei) {
    int i = blockIdx.x * blockDim.x + threadIdx.x;
    if (i < EE) atomicAdd(&g_deg[ei[EE + i]], 1);
}

// ---------------- exclusive scan (single block) ----------------------------
__global__ void scan_kernel() {
    __shared__ int sm[1024];
    __shared__ int carry_s;
    int tid = threadIdx.x;
    if (tid == 0) carry_s = 0;
    __syncthreads();
    for (int base = 0; base < NN; base += 1024) {
        int carry = carry_s;
        int i = base + tid;
        int v = (i < NN) ? g_deg[i] : 0;
        sm[tid] = v;
        __syncthreads();
        for (int off = 1; off < 1024; off <<= 1) {
            int t = (tid >= off) ? sm[tid - off] : 0;
            __syncthreads();
            sm[tid] += t;
            __syncthreads();
        }
        if (i < NN) g_rowptr[i] = carry + sm[tid] - v;
        if (tid == 1023) carry_s = carry + sm[1023];
        __syncthreads();
    }
    if (tid == 0) g_rowptr[NN] = carry_s;
}

// ---------------- scatter into CSR (edges + self loops) --------------------
__global__ void scatter_kernel(const int* __restrict__ ei) {
    int i = blockIdx.x * blockDim.x + threadIdx.x;
    if (i < EE) {
        int s = ei[i];
        int d = ei[EE + i];
        int pos = g_rowptr[d] + atomicAdd(&g_cursor[d], 1);
        g_esrc[pos] = s;
    } else if (i < ET) {
        int n = i - EE;
        int pos = g_rowptr[n] + atomicAdd(&g_cursor[n], 1);
        g_esrc[pos] = n;
    }
}

// ---------------- attention dot products (asrc/adst per node,head) ---------
template <int H, int C>
__global__ void dots_kernel(const float* __restrict__ h,
                            const float* __restrict__ a_src,
                            const float* __restrict__ a_dst,
                            float* __restrict__ asrc, float* __restrict__ adst)
{
    int node = blockIdx.x;
    int w = threadIdx.x / 32, lane = threadIdx.x % 32;
    const float* hp = h + (size_t)node * H * C + w * C;
    float s1 = 0.f, s2 = 0.f;
#pragma unroll
    for (int i = lane; i < C; i += 32) {
        float v = hp[i];
        s1 += v * a_src[w * C + i];
        s2 += v * a_dst[w * C + i];
    }
#pragma unroll
    for (int off = 16; off; off >>= 1) {
        s1 += __shfl_down_sync(0xffffffffu, s1, off);
        s2 += __shfl_down_sync(0xffffffffu, s2, off);
    }
    if (lane == 0) {
        asrc[node * H + w] = s1;
        adst[node * H + w] = s2;
    }
}

// ---------------- block reductions (128 threads) ---------------------------
__device__ __forceinline__ float blockReduceMax128(float v, float* s) {
    int t = threadIdx.x;
    __syncthreads();
    s[t] = v;
    __syncthreads();
    if (t < 64) s[t] = fmaxf(s[t], s[t + 64]);
    __syncthreads();
    if (t < 32) {
        float x = fmaxf(s[t], s[t + 32]);
#pragma unroll
        for (int o = 16; o; o >>= 1) x = fmaxf(x, __shfl_down_sync(0xffffffffu, x, o));
        if (t == 0) s[0] = x;
    }
    __syncthreads();
    float r = s[0];
    __syncthreads();
    return r;
}

__device__ __forceinline__ float blockReduceSum128(float v, float* s) {
    int t = threadIdx.x;
    __syncthreads();
    s[t] = v;
    __syncthreads();
    if (t < 64) s[t] += s[t + 64];
    __syncthreads();
    if (t < 32) {
        float x = s[t] + s[t + 32];
#pragma unroll
        for (int o = 16; o; o >>= 1) x += __shfl_down_sync(0xffffffffu, x, o);
        if (t == 0) s[0] = x;
    }
    __syncthreads();
    float r = s[0];
    __syncthreads();
    return r;
}

// ---------------- fused attention + aggregation per dst node ---------------
// EMIT16: write elu result as bf16 hi/lo (feeds next GEMM); else fp32.
template <int H, int C, bool EMIT16>
__global__ __launch_bounds__(C) void agg_kernel(
    const float* __restrict__ h,
    const float* __restrict__ asrc, const float* __restrict__ adst,
    const float* __restrict__ bias, float* __restrict__ out,
    __nv_bfloat16* __restrict__ outh, __nv_bfloat16* __restrict__ outl)
{
    const int CH = 1024;
    __shared__ int   s_src[CH];
    __shared__ float s_w[CH * H];
    __shared__ float s_red[C];

    int node = blockIdx.x, t = threadIdx.x;
    int beg = g_rowptr[node], end = g_rowptr[node + 1];

    float ad[H], m[H], ssum[H], acc[H];
#pragma unroll
    for (int hh = 0; hh < H; hh++) {
        ad[hh] = adst[node * H + hh];
        m[hh] = -1e30f;
        ssum[hh] = 0.f;
        acc[hh] = 0.f;
    }

    for (int cbeg = beg; cbeg < end; cbeg += CH) {
        int clen = min(CH, end - cbeg);
        float lmax[H];
#pragma unroll
        for (int hh = 0; hh < H; hh++) lmax[hh] = -1e30f;
        for (int i = t; i < clen; i += C) {
            int s = g_esrc[cbeg + i];
            s_src[i] = s;
#pragma unroll
            for (int hh = 0; hh < H; hh++) {
                float l = asrc[s * H + hh] + ad[hh];
                l = l > 0.f ? l : 0.2f * l;
                s_w[i * H + hh] = l;
                lmax[hh] = fmaxf(lmax[hh], l);
            }
        }
        float newm[H], f[H];
#pragma unroll
        for (int hh = 0; hh < H; hh++) {
            float cm = blockReduceMax128(lmax[hh], s_red);
            newm[hh] = fmaxf(m[hh], cm);
            f[hh] = __expf(m[hh] - newm[hh]);
            m[hh] = newm[hh];
        }
        float ls[H];
#pragma unroll
        for (int hh = 0; hh < H; hh++) ls[hh] = 0.f;
        for (int i = t; i < clen; i += C) {
#pragma unroll
            for (int hh = 0; hh < H; hh++) {
                float w = __expf(s_w[i * H + hh] - m[hh]);
                s_w[i * H + hh] = w;
                ls[hh] += w;
            }
        }
#pragma unroll
        for (int hh = 0; hh < H; hh++) {
            float cs = blockReduceSum128(ls[hh], s_red);
            ssum[hh] = ssum[hh] * f[hh] + cs;
            acc[hh] *= f[hh];
        }
#pragma unroll 2
        for (int i = 0; i < clen; i++) {
            int s = s_src[i];
            const float* hp = h + (size_t)s * (H * C);
#pragma unroll
            for (int hh = 0; hh < H; hh++) {
                acc[hh] += s_w[i * H + hh] * hp[hh * C + t];
            }
        }
        __syncthreads();
    }
#pragma unroll
    for (int hh = 0; hh < H; hh++) {
        float v = acc[hh] / ssum[hh] + bias[hh * C + t];
        v = v > 0.f ? v : expm1f(v);
        size_t idx = (size_t)node * H * C + hh * C + t;
        if (EMIT16) {
            __nv_bfloat16 hv, lv;
            split_bf16(v, hv, lv);
            outh[idx] = hv;
            outl[idx] = lv;
        } else {
            out[idx] = v;
        }
    }
}

// ---------------- pooling ---------------------------------------------------
__global__ void pool_kernel(const int* __restrict__ batch) {
    int i = blockIdx.x * blockDim.x + threadIdx.x;
    if (i < NN * HIDC) {
        int node = i >> 7, c = i & 127;
        int g = batch[node];
        atomicAdd(&g_pool[g * HIDC + c], g_out2[i]);
        if (c == 0) atomicAdd(&g_cnt[g], 1.0f);
    }
}

__global__ void final_kernel(const float* __restrict__ Wl,
                             const float* __restrict__ bl,
                             float* __restrict__ out)
{
    __shared__ float s_red[128];
    int g = blockIdx.x, t = threadIdx.x;
    float c = fmaxf(g_cnt[g], 1.0f);
    float v = g_pool[g * HIDC + t] / c * Wl[t];
    float r = blockReduceSum128(v, s_red);
    if (t == 0) out[g] = r + bl[0];
}

// ---------------- launch ----------------------------------------------------
extern "C" void kernel_launch(void* const* d_in, const int* in_sizes, int n_in,
                              void* d_out, int out_size)
{
    const float* x       = (const float*)d_in[0];
    const int*   ei      = (const int*)  d_in[1];
    const int*   batch   = (const int*)  d_in[2];
    const float* W1      = (const float*)d_in[3];
    const float* a_src1  = (const float*)d_in[4];
    const float* a_dst1  = (const float*)d_in[5];
    const float* b1      = (const float*)d_in[6];
    const float* W2      = (const float*)d_in[7];
    const float* a_src2  = (const float*)d_in[8];
    const float* a_dst2  = (const float*)d_in[9];
    const float* b2      = (const float*)d_in[10];
    const float* Wl      = (const float*)d_in[11];
    const float* bl      = (const float*)d_in[12];
    float* out = (float*)d_out;

    float *p_h1, *p_h2, *p_out2, *p_asrc1, *p_adst1, *p_asrc2, *p_adst2;
    __nv_bfloat16 *p_xh, *p_xl, *p_a1h, *p_a1l, *p_w1h, *p_w1l, *p_w2h, *p_w2l;
    cudaGetSymbolAddress((void**)&p_h1,    g_h1);
    cudaGetSymbolAddress((void**)&p_h2,    g_h2);
    cudaGetSymbolAddress((void**)&p_out2,  g_out2);
    cudaGetSymbolAddress((void**)&p_asrc1, g_asrc1);
    cudaGetSymbolAddress((void**)&p_adst1, g_adst1);
    cudaGetSymbolAddress((void**)&p_asrc2, g_asrc2);
    cudaGetSymbolAddress((void**)&p_adst2, g_adst2);
    cudaGetSymbolAddress((void**)&p_xh,  g_xh);
    cudaGetSymbolAddress((void**)&p_xl,  g_xl);
    cudaGetSymbolAddress((void**)&p_a1h, g_a1h);
    cudaGetSymbolAddress((void**)&p_a1l, g_a1l);
    cudaGetSymbolAddress((void**)&p_w1h, g_w1h);
    cudaGetSymbolAddress((void**)&p_w1l, g_w1l);
    cudaGetSymbolAddress((void**)&p_w2h, g_w2h);
    cudaGetSymbolAddress((void**)&p_w2l, g_w2l);

    // build CSR (counting sort by dst, self loops included)
    init_kernel<<<512, 256>>>();
    count_kernel<<<(EE + 255) / 256, 256>>>(ei);
    scan_kernel<<<1, 1024>>>();
    scatter_kernel<<<(ET + 255) / 256, 256>>>(ei);

    // pre-convert inputs/weights to bf16 hi/lo (transposed weights)
    convert_x_kernel<<<(NN * FIN / 4 + 255) / 256, 256>>>(x, NN * FIN);
    convert_w_kernel<<<(FIN * C1 + 255) / 256, 256>>>(W1, p_w1h, p_w1l, FIN, C1);
    convert_w_kernel<<<(C1 * HIDC + 255) / 256, 256>>>(W2, p_w2h, p_w2l, C1, HIDC);

    // layer 1: h1 = x @ W1 (tensor-core, pre-converted operands)
    {
        dim3 grid(C1 / 128, (NN + 127) / 128);
        mma_gemm_kernel<<<grid, 256>>>(p_xh, p_xl, p_w1h, p_w1l, p_h1, NN, C1, FIN);
    }
    dots_kernel<HEADS, HIDC><<<NN, 32 * HEADS>>>(p_h1, a_src1, a_dst1, p_asrc1, p_adst1);
    agg_kernel<HEADS, HIDC, true><<<NN, HIDC>>>(p_h1, p_asrc1, p_adst1, b1,
                                                nullptr, p_a1h, p_a1l);

    // layer 2: h2 = act1 @ W2
    {
        dim3 grid(HIDC / 128, (NN + 127) / 128);
        mma_gemm_kernel<<<grid, 256>>>(p_a1h, p_a1l, p_w2h, p_w2l, p_h2, NN, HIDC, C1);
    }
    dots_kernel<1, HIDC><<<NN, 32>>>(p_h2, a_src2, a_dst2, p_asrc2, p_adst2);
    agg_kernel<1, HIDC, false><<<NN, HIDC>>>(p_h2, p_asrc2, p_adst2, b2,
                                             p_out2, nullptr, nullptr);

    // pooling + linear head
    pool_kernel<<<((size_t)NN * HIDC + 255) / 256, 256>>>(batch);
    final_kernel<<<GG, HIDC>>>(Wl, bl, out);
}

// round 6
// speedup vs baseline: 2.0875x; 1.2325x over previous
#include <cuda_runtime.h>
#include <cuda_bf16.h>
#include <math.h>
#include <cstdint>

// Problem constants
#define NN    50000
#define EE    800000
#define ET    (EE + NN)      // edges + self loops
#define FIN   128
#define HIDC  128
#define HEADS 4
#define GG    512
#define C1    (HEADS * HIDC) // 512

// ---------------- scratch (static device globals; no allocation allowed) ---
__device__ float g_h1[(size_t)NN * C1];      // x @ W1 (fp32, for dots/gather)
__device__ float g_h2[(size_t)NN * HIDC];    // act1 @ W2
__device__ float g_out2[(size_t)NN * HIDC];  // elu(agg2 + b2)
__device__ __nv_bfloat16 g_xh[(size_t)NN * FIN];   // x hi
__device__ __nv_bfloat16 g_xl[(size_t)NN * FIN];   // x lo
__device__ __nv_bfloat16 g_a1h[(size_t)NN * C1];   // act1 hi
__device__ __nv_bfloat16 g_a1l[(size_t)NN * C1];   // act1 lo
__device__ __nv_bfloat16 g_w1h[C1 * FIN];    // W1^T [512][128] hi
__device__ __nv_bfloat16 g_w1l[C1 * FIN];
__device__ __nv_bfloat16 g_w2h[HIDC * C1];   // W2^T [128][512] hi
__device__ __nv_bfloat16 g_w2l[HIDC * C1];
__device__ float g_asrc1[NN * HEADS];
__device__ float g_adst1[NN * HEADS];
__device__ float g_asrc2[NN];
__device__ float g_adst2[NN];
__device__ int   g_deg[NN];
__device__ int   g_rowptr[NN + 1];
__device__ int   g_cursor[NN];
__device__ int   g_esrc[ET];
__device__ float g_pool[GG * HIDC];
__device__ float g_cnt[GG];
__device__ int   g_bsum[64];
__device__ int   g_boff[64];

// ====================== helpers ============================================
__device__ __forceinline__ void split_bf16(float v, __nv_bfloat16& h, __nv_bfloat16& l) {
    h = __float2bfloat16_rn(v);
    l = __float2bfloat16_rn(v - __bfloat162float(h));
}

// ---------------- fused init + conversions ---------------------------------
__global__ void prep_kernel(const float* __restrict__ X,
                            const float* __restrict__ W1,
                            const float* __restrict__ W2) {
    int i0 = blockIdx.x * blockDim.x + threadIdx.x;
    int stride = gridDim.x * blockDim.x;
    for (int k = i0; k < NN; k += stride) { g_deg[k] = 1; g_cursor[k] = 0; }
    for (int k = i0; k < GG * HIDC; k += stride) g_pool[k] = 0.f;
    for (int k = i0; k < GG; k += stride) g_cnt[k] = 0.f;
    for (int k = i0; k < NN * FIN / 4; k += stride) {
        int i = k * 4;
        float4 v = *reinterpret_cast<const float4*>(&X[i]);
        __nv_bfloat16 h[4], l[4];
        split_bf16(v.x, h[0], l[0]); split_bf16(v.y, h[1], l[1]);
        split_bf16(v.z, h[2], l[2]); split_bf16(v.w, h[3], l[3]);
        *reinterpret_cast<uint2*>(&g_xh[i]) = *reinterpret_cast<uint2*>(h);
        *reinterpret_cast<uint2*>(&g_xl[i]) = *reinterpret_cast<uint2*>(l);
    }
    for (int k = i0; k < FIN * C1; k += stride) {
        int kk = k / C1, n = k % C1;
        __nv_bfloat16 h, l;
        split_bf16(W1[k], h, l);
        g_w1h[n * FIN + kk] = h;
        g_w1l[n * FIN + kk] = l;
    }
    for (int k = i0; k < C1 * HIDC; k += stride) {
        int kk = k / HIDC, n = k % HIDC;
        __nv_bfloat16 h, l;
        split_bf16(W2[k], h, l);
        g_w2h[n * C1 + kk] = h;
        g_w2l[n * C1 + kk] = l;
    }
}

// ---------------- degree count ---------------------------------------------
__global__ void count_kernel(const int* __restrict__ ei) {
    int i = blockIdx.x * blockDim.x + threadIdx.x;
    if (i < EE) atomicAdd(&g_deg[ei[EE + i]], 1);
}

// ---------------- parallel 3-phase exclusive scan --------------------------
__global__ void scan1_kernel() {
    __shared__ int sm[1024];
    int tid = threadIdx.x;
    int i = blockIdx.x * 1024 + tid;
    int v = (i < NN) ? g_deg[i] : 0;
    sm[tid] = v;
    __syncthreads();
    for (int off = 1; off < 1024; off <<= 1) {
        int tv = (tid >= off) ? sm[tid - off] : 0;
        __syncthreads();
        sm[tid] += tv;
        __syncthreads();
    }
    if (i < NN) g_rowptr[i] = sm[tid] - v;
    if (tid == 1023) g_bsum[blockIdx.x] = sm[1023];
}

__global__ void scan2_kernel(int nblk) {
    __shared__ int sm[64];
    int tid = threadIdx.x;  // 64 threads
    int v = (tid < nblk) ? g_bsum[tid] : 0;
    sm[tid] = v;
    __syncthreads();
    for (int off = 1; off < 64; off <<= 1) {
        int tv = (tid >= off) ? sm[tid - off] : 0;
        __syncthreads();
        sm[tid] += tv;
        __syncthreads();
    }
    if (tid < nblk) g_boff[tid] = sm[tid] - v;
    if (tid == 63) g_rowptr[NN] = sm[63];
}

__global__ void scan3_kernel() {
    int i = blockIdx.x * blockDim.x + threadIdx.x;
    if (i < NN) g_rowptr[i] += g_boff[i >> 10];
}

// ---------------- scatter into CSR (edges + self loops) --------------------
__global__ void scatter_kernel(const int* __restrict__ ei) {
    int i = blockIdx.x * blockDim.x + threadIdx.x;
    if (i < EE) {
        int s = ei[i];
        int d = ei[EE + i];
        int pos = g_rowptr[d] + atomicAdd(&g_cursor[d], 1);
        g_esrc[pos] = s;
    } else if (i < ET) {
        int n = i - EE;
        int pos = g_rowptr[n] + atomicAdd(&g_cursor[n], 1);
        g_esrc[pos] = n;
    }
}

// ====================== bf16 mma.sync GEMM =================================
#define KC     32
#define APAD   40

__device__ __forceinline__ void mma16816(float* c, const uint32_t* a, const uint32_t* b) {
    asm volatile(
        "mma.sync.aligned.m16n8k16.row.col.f32.bf16.bf16.f32 "
        "{%0,%1,%2,%3}, {%4,%5,%6,%7}, {%8,%9}, {%0,%1,%2,%3};"
        : "+f"(c[0]), "+f"(c[1]), "+f"(c[2]), "+f"(c[3])
        : "r"(a[0]), "r"(a[1]), "r"(a[2]), "r"(a[3]), "r"(b[0]), "r"(b[1]));
}

__global__ __launch_bounds__(256) void mma_gemm_kernel(
    const __nv_bfloat16* __restrict__ Ah, const __nv_bfloat16* __restrict__ Al,
    const __nv_bfloat16* __restrict__ Bth, const __nv_bfloat16* __restrict__ Btl,
    float* __restrict__ C, int M, int Nn, int K)
{
    __shared__ unsigned short Ahs[128 * APAD];
    __shared__ unsigned short Als[128 * APAD];
    __shared__ unsigned short Bhs[128 * APAD];
    __shared__ unsigned short Bls[128 * APAD];

    int tid = threadIdx.x;
    int wid = tid >> 5, lane = tid & 31;
    int warp_m = wid & 3;
    int warp_n = wid >> 2;
    int g = lane >> 2, tg = lane & 3;
    int rowBase = blockIdx.y * 128;
    int colBase = blockIdx.x * 128;

    float acc[2][8][4];
#pragma unroll
    for (int mt = 0; mt < 2; mt++)
#pragma unroll
        for (int nt = 0; nt < 8; nt++)
#pragma unroll
            for (int j = 0; j < 4; j++) acc[mt][nt][j] = 0.f;

    for (int k0 = 0; k0 < K; k0 += KC) {
#pragma unroll
        for (int l = 0; l < 4; l++) {
            int idx = tid + l * 256;
            int row = idx >> 3;
            int q = idx & 7;
            int gr = rowBase + row;
            uint2 vh = make_uint2(0u, 0u), vl = make_uint2(0u, 0u);
            if (gr < M) {
                vh = *reinterpret_cast<const uint2*>(&Ah[(size_t)gr * K + k0 + q * 4]);
                vl = *reinterpret_cast<const uint2*>(&Al[(size_t)gr * K + k0 + q * 4]);
            }
            *reinterpret_cast<uint2*>(&Ahs[row * APAD + q * 4]) = vh;
            *reinterpret_cast<uint2*>(&Als[row * APAD + q * 4]) = vl;
        }
#pragma unroll
        for (int l = 0; l < 4; l++) {
            int idx = tid + l * 256;
            int n = idx >> 3;
            int q = idx & 7;
            uint2 vh = *reinterpret_cast<const uint2*>(&Bth[(size_t)(colBase + n) * K + k0 + q * 4]);
            uint2 vl = *reinterpret_cast<const uint2*>(&Btl[(size_t)(colBase + n) * K + k0 + q * 4]);
            *reinterpret_cast<uint2*>(&Bhs[n * APAD + q * 4]) = vh;
            *reinterpret_cast<uint2*>(&Bls[n * APAD + q * 4]) = vl;
        }
        __syncthreads();

#pragma unroll
        for (int ks = 0; ks < 2; ks++) {
            int kk = ks * 16;
            uint32_t afh[2][4], afl[2][4];
#pragma unroll
            for (int mt = 0; mt < 2; mt++) {
                int r0 = (warp_m * 32 + mt * 16 + g) * APAD + kk + tg * 2;
                int r8 = r0 + 8 * APAD;
                afh[mt][0] = *reinterpret_cast<uint32_t*>(&Ahs[r0]);
                afh[mt][1] = *reinterpret_cast<uint32_t*>(&Ahs[r8]);
                afh[mt][2] = *reinterpret_cast<uint32_t*>(&Ahs[r0 + 8]);
                afh[mt][3] = *reinterpret_cast<uint32_t*>(&Ahs[r8 + 8]);
                afl[mt][0] = *reinterpret_cast<uint32_t*>(&Als[r0]);
                afl[mt][1] = *reinterpret_cast<uint32_t*>(&Als[r8]);
                afl[mt][2] = *reinterpret_cast<uint32_t*>(&Als[r0 + 8]);
                afl[mt][3] = *reinterpret_cast<uint32_t*>(&Als[r8 + 8]);
            }
#pragma unroll
            for (int nt = 0; nt < 8; nt++) {
                int nb = (warp_n * 64 + nt * 8 + g) * APAD + kk + tg * 2;
                uint32_t bfh[2], bfl[2];
                bfh[0] = *reinterpret_cast<uint32_t*>(&Bhs[nb]);
                bfh[1] = *reinterpret_cast<uint32_t*>(&Bhs[nb + 8]);
                bfl[0] = *reinterpret_cast<uint32_t*>(&Bls[nb]);
                bfl[1] = *reinterpret_cast<uint32_t*>(&Bls[nb + 8]);
#pragma unroll
                for (int mt = 0; mt < 2; mt++) {
                    mma16816(acc[mt][nt], afh[mt], bfh);
                    mma16816(acc[mt][nt], afh[mt], bfl);
                    mma16816(acc[mt][nt], afl[mt], bfh);
                }
            }
        }
        __syncthreads();
    }

#pragma unroll
    for (int mt = 0; mt < 2; mt++) {
        int r0 = rowBase + warp_m * 32 + mt * 16 + g;
#pragma unroll
        for (int nt = 0; nt < 8; nt++) {
            int col = colBase + warp_n * 64 + nt * 8 + tg * 2;
            if (r0 < M)
                *reinterpret_cast<float2*>(&C[(size_t)r0 * Nn + col]) =
                    make_float2(acc[mt][nt][0], acc[mt][nt][1]);
            if (r0 + 8 < M)
                *reinterpret_cast<float2*>(&C[(size_t)(r0 + 8) * Nn + col]) =
                    make_float2(acc[mt][nt][2], acc[mt][nt][3]);
        }
    }
}

// ---------------- attention dot products -----------------------------------
template <int H, int C>
__global__ void dots_kernel(const float* __restrict__ h,
                            const float* __restrict__ a_src,
                            const float* __restrict__ a_dst,
                            float* __restrict__ asrc, float* __restrict__ adst)
{
    int node = blockIdx.x;
    int w = threadIdx.x / 32, lane = threadIdx.x % 32;
    const float* hp = h + (size_t)node * H * C + w * C;
    float s1 = 0.f, s2 = 0.f;
#pragma unroll
    for (int i = lane; i < C; i += 32) {
        float v = hp[i];
        s1 += v * a_src[w * C + i];
        s2 += v * a_dst[w * C + i];
    }
#pragma unroll
    for (int off = 16; off; off >>= 1) {
        s1 += __shfl_down_sync(0xffffffffu, s1, off);
        s2 += __shfl_down_sync(0xffffffffu, s2, off);
    }
    if (lane == 0) {
        asrc[node * H + w] = s1;
        adst[node * H + w] = s2;
    }
}

// ---------------- fused attention + aggregation per dst node ---------------
// Warp w owns softmax for head w (shuffle-only reductions); all 128 threads
// aggregate channels. CH=64 sized for Poisson(17) degrees; chunk loop keeps
// correctness for any degree.
template <int H, int C, bool EMIT16>
__global__ __launch_bounds__(C) void agg_kernel(
    const float* __restrict__ h,
    const float* __restrict__ asrc, const float* __restrict__ adst,
    const float* __restrict__ bias, float* __restrict__ out,
    __nv_bfloat16* __restrict__ outh, __nv_bfloat16* __restrict__ outl)
{
    const int CH = 64;
    __shared__ int   s_src[CH];
    __shared__ float s_w[CH * H];
    __shared__ float s_f[H];
    __shared__ float s_den[H];

    int node = blockIdx.x, t = threadIdx.x;
    int wid = t >> 5, lane = t & 31;
    int beg = g_rowptr[node], end = g_rowptr[node + 1];

    float acc[H];
#pragma unroll
    for (int hh = 0; hh < H; hh++) acc[hh] = 0.f;

    float m = -1e30f, ssum = 0.f, ad = 0.f;
    if (wid < H) ad = adst[node * H + wid];

    for (int cbeg = beg; cbeg < end; cbeg += CH) {
        int clen = min(CH, end - cbeg);
        if (wid < H) {
            float lmax = -1e30f;
            for (int i = lane; i < clen; i += 32) {
                int s = g_esrc[cbeg + i];
                if (wid == 0) s_src[i] = s;
                float l = asrc[s * H + wid] + ad;
                l = l > 0.f ? l : 0.2f * l;
                s_w[i * H + wid] = l;
                lmax = fmaxf(lmax, l);
            }
#pragma unroll
            for (int o = 16; o; o >>= 1)
                lmax = fmaxf(lmax, __shfl_xor_sync(0xffffffffu, lmax, o));
            float newm = fmaxf(m, lmax);
            float f = __expf(m - newm);
            m = newm;
            float lsum = 0.f;
            for (int i = lane; i < clen; i += 32) {
                float w = __expf(s_w[i * H + wid] - m);
                s_w[i * H + wid] = w;
                lsum += w;
            }
#pragma unroll
            for (int o = 16; o; o >>= 1)
                lsum += __shfl_xor_sync(0xffffffffu, lsum, o);
            ssum = ssum * f + lsum;
            if (lane == 0) s_f[wid] = f;
        }
        __syncthreads();
#pragma unroll
        for (int hh = 0; hh < H; hh++) acc[hh] *= s_f[hh];

        int i = 0;
        for (; i + 4 <= clen; i += 4) {
            int s0 = s_src[i], s1 = s_src[i + 1], s2 = s_src[i + 2], s3 = s_src[i + 3];
            const float* p0 = h + (size_t)s0 * (H * C) + t;
            const float* p1 = h + (size_t)s1 * (H * C) + t;
            const float* p2 = h + (size_t)s2 * (H * C) + t;
            const float* p3 = h + (size_t)s3 * (H * C) + t;
#pragma unroll
            for (int hh = 0; hh < H; hh++) {
                float w0 = s_w[(i + 0) * H + hh], w1 = s_w[(i + 1) * H + hh];
                float w2 = s_w[(i + 2) * H + hh], w3 = s_w[(i + 3) * H + hh];
                acc[hh] += w0 * p0[hh * C] + w1 * p1[hh * C]
                         + w2 * p2[hh * C] + w3 * p3[hh * C];
            }
        }
        for (; i < clen; i++) {
            int s = s_src[i];
            const float* p = h + (size_t)s * (H * C) + t;
#pragma unroll
            for (int hh = 0; hh < H; hh++)
                acc[hh] += s_w[i * H + hh] * p[hh * C];
        }
        __syncthreads();
    }
    if (wid < H && lane == 0) s_den[wid] = ssum;
    __syncthreads();
#pragma unroll
    for (int hh = 0; hh < H; hh++) {
        float v = acc[hh] / s_den[hh] + bias[hh * C + t];
        v = v > 0.f ? v : expm1f(v);
        size_t idx = (size_t)node * H * C + hh * C + t;
        if (EMIT16) {
            __nv_bfloat16 hv, lv;
            split_bf16(v, hv, lv);
            outh[idx] = hv;
            outl[idx] = lv;
        } else {
            out[idx] = v;
        }
    }
}

// ---------------- pooling ---------------------------------------------------
__global__ void pool_kernel(const int* __restrict__ batch) {
    int i = blockIdx.x * blockDim.x + threadIdx.x;
    if (i < NN * HIDC) {
        int node = i >> 7, c = i & 127;
        int g = batch[node];
        atomicAdd(&g_pool[g * HIDC + c], g_out2[i]);
        if (c == 0) atomicAdd(&g_cnt[g], 1.0f);
    }
}

__global__ void final_kernel(const float* __restrict__ Wl,
                             const float* __restrict__ bl,
                             float* __restrict__ out)
{
    __shared__ float s_red[128];
    int g = blockIdx.x, t = threadIdx.x;
    int lane = t & 31, w = t >> 5;
    float c = fmaxf(g_cnt[g], 1.0f);
    float v = g_pool[g * HIDC + t] / c * Wl[t];
#pragma unroll
    for (int o = 16; o; o >>= 1) v += __shfl_down_sync(0xffffffffu, v, o);
    if (lane == 0) s_red[w] = v;
    __syncthreads();
    if (t == 0) out[g] = s_red[0] + s_red[1] + s_red[2] + s_red[3] + bl[0];
}

// ---------------- launch ----------------------------------------------------
extern "C" void kernel_launch(void* const* d_in, const int* in_sizes, int n_in,
                              void* d_out, int out_size)
{
    const float* x       = (const float*)d_in[0];
    const int*   ei      = (const int*)  d_in[1];
    const int*   batch   = (const int*)  d_in[2];
    const float* W1      = (const float*)d_in[3];
    const float* a_src1  = (const float*)d_in[4];
    const float* a_dst1  = (const float*)d_in[5];
    const float* b1      = (const float*)d_in[6];
    const float* W2      = (const float*)d_in[7];
    const float* a_src2  = (const float*)d_in[8];
    const float* a_dst2  = (const float*)d_in[9];
    const float* b2      = (const float*)d_in[10];
    const float* Wl      = (const float*)d_in[11];
    const float* bl      = (const float*)d_in[12];
    float* out = (float*)d_out;

    float *p_h1, *p_h2, *p_out2, *p_asrc1, *p_adst1, *p_asrc2, *p_adst2;
    __nv_bfloat16 *p_xh, *p_xl, *p_a1h, *p_a1l, *p_w1h, *p_w1l, *p_w2h, *p_w2l;
    cudaGetSymbolAddress((void**)&p_h1,    g_h1);
    cudaGetSymbolAddress((void**)&p_h2,    g_h2);
    cudaGetSymbolAddress((void**)&p_out2,  g_out2);
    cudaGetSymbolAddress((void**)&p_asrc1, g_asrc1);
    cudaGetSymbolAddress((void**)&p_adst1, g_adst1);
    cudaGetSymbolAddress((void**)&p_asrc2, g_asrc2);
    cudaGetSymbolAddress((void**)&p_adst2, g_adst2);
    cudaGetSymbolAddress((void**)&p_xh,  g_xh);
    cudaGetSymbolAddress((void**)&p_xl,  g_xl);
    cudaGetSymbolAddress((void**)&p_a1h, g_a1h);
    cudaGetSymbolAddress((void**)&p_a1l, g_a1l);
    cudaGetSymbolAddress((void**)&p_w1h, g_w1h);
    cudaGetSymbolAddress((void**)&p_w1l, g_w1l);
    cudaGetSymbolAddress((void**)&p_w2h, g_w2h);
    cudaGetSymbolAddress((void**)&p_w2l, g_w2l);

    const int NBLK = (NN + 1023) / 1024;  // 49

    // fused init + bf16 conversions
    prep_kernel<<<1024, 256>>>(x, W1, W2);
    // CSR build
    count_kernel<<<(EE + 255) / 256, 256>>>(ei);
    scan1_kernel<<<NBLK, 1024>>>();
    scan2_kernel<<<1, 64>>>(NBLK);
    scan3_kernel<<<(NN + 255) / 256, 256>>>();
    scatter_kernel<<<(ET + 255) / 256, 256>>>(ei);

    // layer 1
    {
        dim3 grid(C1 / 128, (NN + 127) / 128);
        mma_gemm_kernel<<<grid, 256>>>(p_xh, p_xl, p_w1h, p_w1l, p_h1, NN, C1, FIN);
    }
    dots_kernel<HEADS, HIDC><<<NN, 32 * HEADS>>>(p_h1, a_src1, a_dst1, p_asrc1, p_adst1);
    agg_kernel<HEADS, HIDC, true><<<NN, HIDC>>>(p_h1, p_asrc1, p_adst1, b1,
                                                nullptr, p_a1h, p_a1l);

    // layer 2
    {
        dim3 grid(HIDC / 128, (NN + 127) / 128);
        mma_gemm_kernel<<<grid, 256>>>(p_a1h, p_a1l, p_w2h, p_w2l, p_h2, NN, HIDC, C1);
    }
    dots_kernel<1, HIDC><<<NN, 32>>>(p_h2, a_src2, a_dst2, p_asrc2, p_adst2);
    agg_kernel<1, HIDC, false><<<NN, HIDC>>>(p_h2, p_asrc2, p_adst2, b2,
                                             p_out2, nullptr, nullptr);

    // pooling + linear head
    pool_kernel<<<((size_t)NN * HIDC + 255) / 256, 256>>>(batch);
    final_kernel<<<GG, HIDC>>>(Wl, bl, out);
}

// round 10
// speedup vs baseline: 2.4140x; 1.1564x over previous
#include <cuda_runtime.h>
#include <cuda_bf16.h>
#include <math.h>
#include <cstdint>

// Problem constants
#define NN    50000
#define EE    800000
#define ET    (EE + NN)      // edges + self loops
#define FIN   128
#define HIDC  128
#define HEADS 4
#define GG    512
#define C1    (HEADS * HIDC) // 512

// ---------------- scratch (static device globals; no allocation allowed) ---
__device__ __nv_bfloat16 g_h1b[(size_t)NN * C1];   // x @ W1 (bf16, gather src)
__device__ __nv_bfloat16 g_h2b[(size_t)NN * HIDC]; // act1 @ W2 (bf16)
__device__ float g_out2[(size_t)NN * HIDC];  // elu(agg2 + b2)
__device__ __nv_bfloat16 g_xh[(size_t)NN * FIN];   // x hi
__device__ __nv_bfloat16 g_xl[(size_t)NN * FIN];   // x lo
__device__ __nv_bfloat16 g_a1h[(size_t)NN * C1];   // act1 hi
__device__ __nv_bfloat16 g_a1l[(size_t)NN * C1];   // act1 lo
__device__ __nv_bfloat16 g_w1h[C1 * FIN];    // W1^T [512][128] hi
__device__ __nv_bfloat16 g_w1l[C1 * FIN];
__device__ __nv_bfloat16 g_w2h[HIDC * C1];   // W2^T [128][512] hi
__device__ __nv_bfloat16 g_w2l[HIDC * C1];
__device__ float g_asrc1[NN * HEADS];
__device__ float g_adst1[NN * HEADS];
__device__ float g_asrc2[NN];
__device__ float g_adst2[NN];
__device__ int   g_deg[NN];
__device__ int   g_rowptr[NN + 1];
__device__ int   g_cursor[NN];
__device__ int   g_esrc[ET];
__device__ float g_pool[GG * HIDC];
__device__ float g_cnt[GG];
__device__ int   g_bsum[64];
__device__ int   g_boff[64];

// ====================== helpers ============================================
__device__ __forceinline__ void split_bf16(float v, __nv_bfloat16& h, __nv_bfloat16& l) {
    h = __float2bfloat16_rn(v);
    l = __float2bfloat16_rn(v - __bfloat162float(h));
}

// ---------------- fused init + conversions ---------------------------------
__global__ void prep_kernel(const float* __restrict__ X,
                            const float* __restrict__ W1,
                            const float* __restrict__ W2) {
    int i0 = blockIdx.x * blockDim.x + threadIdx.x;
    int stride = gridDim.x * blockDim.x;
    for (int k = i0; k < NN; k += stride) { g_deg[k] = 1; g_cursor[k] = 0; }
    for (int k = i0; k < GG * HIDC; k += stride) g_pool[k] = 0.f;
    for (int k = i0; k < GG; k += stride) g_cnt[k] = 0.f;
    for (int k = i0; k < NN * FIN / 4; k += stride) {
        int i = k * 4;
        float4 v = *reinterpret_cast<const float4*>(&X[i]);
        __nv_bfloat16 h[4], l[4];
        split_bf16(v.x, h[0], l[0]); split_bf16(v.y, h[1], l[1]);
        split_bf16(v.z, h[2], l[2]); split_bf16(v.w, h[3], l[3]);
        *reinterpret_cast<uint2*>(&g_xh[i]) = *reinterpret_cast<uint2*>(h);
        *reinterpret_cast<uint2*>(&g_xl[i]) = *reinterpret_cast<uint2*>(l);
    }
    for (int k = i0; k < FIN * C1; k += stride) {
        int kk = k / C1, n = k % C1;
        __nv_bfloat16 h, l;
        split_bf16(W1[k], h, l);
        g_w1h[n * FIN + kk] = h;
        g_w1l[n * FIN + kk] = l;
    }
    for (int k = i0; k < C1 * HIDC; k += stride) {
        int kk = k / HIDC, n = k % HIDC;
        __nv_bfloat16 h, l;
        split_bf16(W2[k], h, l);
        g_w2h[n * C1 + kk] = h;
        g_w2l[n * C1 + kk] = l;
    }
}

// ---------------- degree count ---------------------------------------------
__global__ void count_kernel(const int* __restrict__ ei) {
    int i = blockIdx.x * blockDim.x + threadIdx.x;
    if (i < EE) atomicAdd(&g_deg[ei[EE + i]], 1);
}

// ---------------- parallel 3-phase exclusive scan --------------------------
__global__ void scan1_kernel() {
    __shared__ int sm[1024];
    int tid = threadIdx.x;
    int i = blockIdx.x * 1024 + tid;
    int v = (i < NN) ? g_deg[i] : 0;
    sm[tid] = v;
    __syncthreads();
    for (int off = 1; off < 1024; off <<= 1) {
        int tv = (tid >= off) ? sm[tid - off] : 0;
        __syncthreads();
        sm[tid] += tv;
        __syncthreads();
    }
    if (i < NN) g_rowptr[i] = sm[tid] - v;
    if (tid == 1023) g_bsum[blockIdx.x] = sm[1023];
}

__global__ void scan2_kernel(int nblk) {
    __shared__ int sm[64];
    int tid = threadIdx.x;
    int v = (tid < nblk) ? g_bsum[tid] : 0;
    sm[tid] = v;
    __syncthreads();
    for (int off = 1; off < 64; off <<= 1) {
        int tv = (tid >= off) ? sm[tid - off] : 0;
        __syncthreads();
        sm[tid] += tv;
        __syncthreads();
    }
    if (tid < nblk) g_boff[tid] = sm[tid] - v;
    if (tid == 63) g_rowptr[NN] = sm[63];
}

__global__ void scan3_kernel() {
    int i = blockIdx.x * blockDim.x + threadIdx.x;
    if (i < NN) g_rowptr[i] += g_boff[i >> 10];
}

// ---------------- scatter into CSR (edges + self loops) --------------------
__global__ void scatter_kernel(const int* __restrict__ ei) {
    int i = blockIdx.x * blockDim.x + threadIdx.x;
    if (i < EE) {
        int s = ei[i];
        int d = ei[EE + i];
        int pos = g_rowptr[d] + atomicAdd(&g_cursor[d], 1);
        g_esrc[pos] = s;
    } else if (i < ET) {
        int n = i - EE;
        int pos = g_rowptr[n] + atomicAdd(&g_cursor[n], 1);
        g_esrc[pos] = n;
    }
}

// ====================== bf16 mma.sync GEMM + fused dots ====================
// C[M,Nn] = A[M,K] @ B[K,Nn]; bf16 hi/lo split inputs, bf16 output.
// Each column-block covers one head's 128 channels -> computes asrc/adst
// for its 128 rows directly from fp32 accumulators (no dots kernel).
#define KC     32
#define APAD   40

__device__ __forceinline__ void mma16816(float* c, const uint32_t* a, const uint32_t* b) {
    asm volatile(
        "mma.sync.aligned.m16n8k16.row.col.f32.bf16.bf16.f32 "
        "{%0,%1,%2,%3}, {%4,%5,%6,%7}, {%8,%9}, {%0,%1,%2,%3};"
        : "+f"(c[0]), "+f"(c[1]), "+f"(c[2]), "+f"(c[3])
        : "r"(a[0]), "r"(a[1]), "r"(a[2]), "r"(a[3]), "r"(b[0]), "r"(b[1]));
}

__global__ __launch_bounds__(256) void mma_gemm_kernel(
    const __nv_bfloat16* __restrict__ Ah, const __nv_bfloat16* __restrict__ Al,
    const __nv_bfloat16* __restrict__ Bth, const __nv_bfloat16* __restrict__ Btl,
    __nv_bfloat16* __restrict__ Cb,
    const float* __restrict__ avs, const float* __restrict__ avd,
    float* __restrict__ asrc_out, float* __restrict__ adst_out,
    int M, int Nn, int K, int H)
{
    __shared__ unsigned short Ahs[128 * APAD];
    __shared__ unsigned short Als[128 * APAD];
    __shared__ unsigned short Bhs[128 * APAD];
    __shared__ unsigned short Bls[128 * APAD];
    __shared__ float s_dt[2][128][2];

    int tid = threadIdx.x;
    int wid = tid >> 5, lane = tid & 31;
    int warp_m = wid & 3;
    int warp_n = wid >> 2;
    int g = lane >> 2, tg = lane & 3;
    int rowBase = blockIdx.y * 128;
    int colBase = blockIdx.x * 128;
    int head = blockIdx.x;

    float acc[2][8][4];
#pragma unroll
    for (int mt = 0; mt < 2; mt++)
#pragma unroll
        for (int nt = 0; nt < 8; nt++)
#pragma unroll
            for (int j = 0; j < 4; j++) acc[mt][nt][j] = 0.f;

    for (int k0 = 0; k0 < K; k0 += KC) {
#pragma unroll
        for (int l = 0; l < 4; l++) {
            int idx = tid + l * 256;
            int row = idx >> 3;
            int q = idx & 7;
            int gr = rowBase + row;
            uint2 vh = make_uint2(0u, 0u), vl = make_uint2(0u, 0u);
            if (gr < M) {
                vh = *reinterpret_cast<const uint2*>(&Ah[(size_t)gr * K + k0 + q * 4]);
                vl = *reinterpret_cast<const uint2*>(&Al[(size_t)gr * K + k0 + q * 4]);
            }
            *reinterpret_cast<uint2*>(&Ahs[row * APAD + q * 4]) = vh;
            *reinterpret_cast<uint2*>(&Als[row * APAD + q * 4]) = vl;
        }
#pragma unroll
        for (int l = 0; l < 4; l++) {
            int idx = tid + l * 256;
            int n = idx >> 3;
            int q = idx & 7;
            uint2 vh = *reinterpret_cast<const uint2*>(&Bth[(size_t)(colBase + n) * K + k0 + q * 4]);
            uint2 vl = *reinterpret_cast<const uint2*>(&Btl[(size_t)(colBase + n) * K + k0 + q * 4]);
            *reinterpret_cast<uint2*>(&Bhs[n * APAD + q * 4]) = vh;
            *reinterpret_cast<uint2*>(&Bls[n * APAD + q * 4]) = vl;
        }
        __syncthreads();

#pragma unroll
        for (int ks = 0; ks < 2; ks++) {
            int kk = ks * 16;
            uint32_t afh[2][4], afl[2][4];
#pragma unroll
            for (int mt = 0; mt < 2; mt++) {
                int r0 = (warp_m * 32 + mt * 16 + g) * APAD + kk + tg * 2;
                int r8 = r0 + 8 * APAD;
                afh[mt][0] = *reinterpret_cast<uint32_t*>(&Ahs[r0]);
                afh[mt][1] = *reinterpret_cast<uint32_t*>(&Ahs[r8]);
                afh[mt][2] = *reinterpret_cast<uint32_t*>(&Ahs[r0 + 8]);
                afh[mt][3] = *reinterpret_cast<uint32_t*>(&Ahs[r8 + 8]);
                afl[mt][0] = *reinterpret_cast<uint32_t*>(&Als[r0]);
                afl[mt][1] = *reinterpret_cast<uint32_t*>(&Als[r8]);
                afl[mt][2] = *reinterpret_cast<uint32_t*>(&Als[r0 + 8]);
                afl[mt][3] = *reinterpret_cast<uint32_t*>(&Als[r8 + 8]);
            }
#pragma unroll
            for (int nt = 0; nt < 8; nt++) {
                int nb = (warp_n * 64 + nt * 8 + g) * APAD + kk + tg * 2;
                uint32_t bfh[2], bfl[2];
                bfh[0] = *reinterpret_cast<uint32_t*>(&Bhs[nb]);
                bfh[1] = *reinterpret_cast<uint32_t*>(&Bhs[nb + 8]);
                bfl[0] = *reinterpret_cast<uint32_t*>(&Bls[nb]);
                bfl[1] = *reinterpret_cast<uint32_t*>(&Bls[nb + 8]);
#pragma unroll
                for (int mt = 0; mt < 2; mt++) {
                    mma16816(acc[mt][nt], afh[mt], bfh);
                    mma16816(acc[mt][nt], afh[mt], bfl);
                    mma16816(acc[mt][nt], afl[mt], bfh);
                }
            }
        }
        __syncthreads();
    }

    // ---- epilogue: bf16 store + fused attention dots ----
    float ps[2][2] = {{0.f, 0.f}, {0.f, 0.f}};
    float pd[2][2] = {{0.f, 0.f}, {0.f, 0.f}};
#pragma unroll
    for (int nt = 0; nt < 8; nt++) {
        int c0 = colBase + warp_n * 64 + nt * 8 + tg * 2;
        float as0 = avs[c0], as1 = avs[c0 + 1];
        float ad0 = avd[c0], ad1 = avd[c0 + 1];
#pragma unroll
        for (int mt = 0; mt < 2; mt++) {
            int r0 = rowBase + warp_m * 32 + mt * 16 + g;
            __nv_bfloat162 v01 = __floats2bfloat162_rn(acc[mt][nt][0], acc[mt][nt][1]);
            __nv_bfloat162 v23 = __floats2bfloat162_rn(acc[mt][nt][2], acc[mt][nt][3]);
            if (r0 < M)
                *reinterpret_cast<__nv_bfloat162*>(&Cb[(size_t)r0 * Nn + c0]) = v01;
            if (r0 + 8 < M)
                *reinterpret_cast<__nv_bfloat162*>(&Cb[(size_t)(r0 + 8) * Nn + c0]) = v23;
            ps[mt][0] += acc[mt][nt][0] * as0 + acc[mt][nt][1] * as1;
            pd[mt][0] += acc[mt][nt][0] * ad0 + acc[mt][nt][1] * ad1;
            ps[mt][1] += acc[mt][nt][2] * as0 + acc[mt][nt][3] * as1;
            pd[mt][1] += acc[mt][nt][2] * ad0 + acc[mt][nt][3] * ad1;
        }
    }
    // reduce over the 4 tg lanes (xor 1,2 stays in group)
#pragma unroll
    for (int mt = 0; mt < 2; mt++)
#pragma unroll
        for (int hf = 0; hf < 2; hf++) {
            ps[mt][hf] += __shfl_xor_sync(0xffffffffu, ps[mt][hf], 1);
            ps[mt][hf] += __shfl_xor_sync(0xffffffffu, ps[mt][hf], 2);
            pd[mt][hf] += __shfl_xor_sync(0xffffffffu, pd[mt][hf], 1);
            pd[mt][hf] += __shfl_xor_sync(0xffffffffu, pd[mt][hf], 2);
        }
    if (tg == 0) {
#pragma unroll
        for (int mt = 0; mt < 2; mt++)
#pragma unroll
            for (int hf = 0; hf < 2; hf++) {
                int lr = warp_m * 32 + mt * 16 + g + hf * 8;
                s_dt[0][lr][warp_n] = ps[mt][hf];
                s_dt[1][lr][warp_n] = pd[mt][hf];
            }
    }
    __syncthreads();
    if (tid < 128) {
        int grow = rowBase + tid;
        if (grow < M) {
            asrc_out[grow * H + head] = s_dt[0][tid][0] + s_dt[0][tid][1];
            adst_out[grow * H + head] = s_dt[1][tid][0] + s_dt[1][tid][1];
        }
    }
}

// ---------------- fused attention + aggregation per dst node ---------------
// Warp w owns softmax for head w; h gathered as bf16.
template <int H, int C, bool EMIT16>
__global__ __launch_bounds__(C) void agg_kernel(
    const __nv_bfloat16* __restrict__ h,
    const float* __restrict__ asrc, const float* __restrict__ adst,
    const float* __restrict__ bias, float* __restrict__ out,
    __nv_bfloat16* __restrict__ outh, __nv_bfloat16* __restrict__ outl)
{
    const int CH = 64;
    __shared__ int   s_src[CH];
    __shared__ float s_w[CH * H];
    __shared__ float s_f[H];
    __shared__ float s_den[H];

    int node = blockIdx.x, t = threadIdx.x;
    int wid = t >> 5, lane = t & 31;
    int beg = g_rowptr[node], end = g_rowptr[node + 1];

    float acc[H];
#pragma unroll
    for (int hh = 0; hh < H; hh++) acc[hh] = 0.f;

    float m = -1e30f, ssum = 0.f, ad = 0.f;
    if (wid < H) ad = adst[node * H + wid];

    for (int cbeg = beg; cbeg < end; cbeg += CH) {
        int clen = min(CH, end - cbeg);
        if (wid < H) {
            float lmax = -1e30f;
            for (int i = lane; i < clen; i += 32) {
                int s = g_esrc[cbeg + i];
                if (wid == 0) s_src[i] = s;
                float l = asrc[s * H + wid] + ad;
                l = l > 0.f ? l : 0.2f * l;
                s_w[i * H + wid] = l;
                lmax = fmaxf(lmax, l);
            }
#pragma unroll
            for (int o = 16; o; o >>= 1)
                lmax = fmaxf(lmax, __shfl_xor_sync(0xffffffffu, lmax, o));
            float newm = fmaxf(m, lmax);
            float f = __expf(m - newm);
            m = newm;
            float lsum = 0.f;
            for (int i = lane; i < clen; i += 32) {
                float w = __expf(s_w[i * H + wid] - m);
                s_w[i * H + wid] = w;
                lsum += w;
            }
#pragma unroll
            for (int o = 16; o; o >>= 1)
                lsum += __shfl_xor_sync(0xffffffffu, lsum, o);
            ssum = ssum * f + lsum;
            if (lane == 0) s_f[wid] = f;
        }
        __syncthreads();
#pragma unroll
        for (int hh = 0; hh < H; hh++) acc[hh] *= s_f[hh];

        int i = 0;
        for (; i + 4 <= clen; i += 4) {
            int s0 = s_src[i], s1 = s_src[i + 1], s2 = s_src[i + 2], s3 = s_src[i + 3];
            const __nv_bfloat16* p0 = h + (size_t)s0 * (H * C) + t;
            const __nv_bfloat16* p1 = h + (size_t)s1 * (H * C) + t;
            const __nv_bfloat16* p2 = h + (size_t)s2 * (H * C) + t;
            const __nv_bfloat16* p3 = h + (size_t)s3 * (H * C) + t;
#pragma unroll
            for (int hh = 0; hh < H; hh++) {
                float w0 = s_w[(i + 0) * H + hh], w1 = s_w[(i + 1) * H + hh];
                float w2 = s_w[(i + 2) * H + hh], w3 = s_w[(i + 3) * H + hh];
                acc[hh] += w0 * __bfloat162float(p0[hh * C])
                         + w1 * __bfloat162float(p1[hh * C])
                         + w2 * __bfloat162float(p2[hh * C])
                         + w3 * __bfloat162float(p3[hh * C]);
            }
        }
        for (; i < clen; i++) {
            int s = s_src[i];
            const __nv_bfloat16* p = h + (size_t)s * (H * C) + t;
#pragma unroll
            for (int hh = 0; hh < H; hh++)
                acc[hh] += s_w[i * H + hh] * __bfloat162float(p[hh * C]);
        }
        __syncthreads();
    }
    if (wid < H && lane == 0) s_den[wid] = ssum;
    __syncthreads();
#pragma unroll
    for (int hh = 0; hh < H; hh++) {
        float v = acc[hh] / s_den[hh] + bias[hh * C + t];
        v = v > 0.f ? v : expm1f(v);
        size_t idx = (size_t)node * H * C + hh * C + t;
        if (EMIT16) {
            __nv_bfloat16 hv, lv;
            split_bf16(v, hv, lv);
            outh[idx] = hv;
            outl[idx] = lv;
        } else {
            out[idx] = v;
        }
    }
}

// ---------------- pooling ---------------------------------------------------
__global__ void pool_kernel(const int* __restrict__ batch) {
    int i = blockIdx.x * blockDim.x + threadIdx.x;
    if (i < NN * HIDC) {
        int node = i >> 7, c = i & 127;
        int g = batch[node];
        atomicAdd(&g_pool[g * HIDC + c], g_out2[i]);
        if (c == 0) atomicAdd(&g_cnt[g], 1.0f);
    }
}

__global__ void final_kernel(const float* __restrict__ Wl,
                             const float* __restrict__ bl,
                             float* __restrict__ out)
{
    __shared__ float s_red[4];
    int g = blockIdx.x, t = threadIdx.x;
    int lane = t & 31, w = t >> 5;
    float c = fmaxf(g_cnt[g], 1.0f);
    float v = g_pool[g * HIDC + t] / c * Wl[t];
#pragma unroll
    for (int o = 16; o; o >>= 1) v += __shfl_down_sync(0xffffffffu, v, o);
    if (lane == 0) s_red[w] = v;
    __syncthreads();
    if (t == 0) out[g] = s_red[0] + s_red[1] + s_red[2] + s_red[3] + bl[0];
}

// ---------------- launch ----------------------------------------------------
extern "C" void kernel_launch(void* const* d_in, const int* in_sizes, int n_in,
                              void* d_out, int out_size)
{
    const float* x       = (const float*)d_in[0];
    const int*   ei      = (const int*)  d_in[1];
    const int*   batch   = (const int*)  d_in[2];
    const float* W1      = (const float*)d_in[3];
    const float* a_src1  = (const float*)d_in[4];
    const float* a_dst1  = (const float*)d_in[5];
    const float* b1      = (const float*)d_in[6];
    const float* W2      = (const float*)d_in[7];
    const float* a_src2  = (const float*)d_in[8];
    const float* a_dst2  = (const float*)d_in[9];
    const float* b2      = (const float*)d_in[10];
    const float* Wl      = (const float*)d_in[11];
    const float* bl      = (const float*)d_in[12];
    float* out = (float*)d_out;

    float *p_out2, *p_asrc1, *p_adst1, *p_asrc2, *p_adst2;
    __nv_bfloat16 *p_h1b, *p_h2b, *p_xh, *p_xl, *p_a1h, *p_a1l, *p_w1h, *p_w1l, *p_w2h, *p_w2l;
    cudaGetSymbolAddress((void**)&p_h1b,   g_h1b);
    cudaGetSymbolAddress((void**)&p_h2b,   g_h2b);
    cudaGetSymbolAddress((void**)&p_out2,  g_out2);
    cudaGetSymbolAddress((void**)&p_asrc1, g_asrc1);
    cudaGetSymbolAddress((void**)&p_adst1, g_adst1);
    cudaGetSymbolAddress((void**)&p_asrc2, g_asrc2);
    cudaGetSymbolAddress((void**)&p_adst2, g_adst2);
    cudaGetSymbolAddress((void**)&p_xh,  g_xh);
    cudaGetSymbolAddress((void**)&p_xl,  g_xl);
    cudaGetSymbolAddress((void**)&p_a1h, g_a1h);
    cudaGetSymbolAddress((void**)&p_a1l, g_a1l);
    cudaGetSymbolAddress((void**)&p_w1h, g_w1h);
    cudaGetSymbolAddress((void**)&p_w1l, g_w1l);
    cudaGetSymbolAddress((void**)&p_w2h, g_w2h);
    cudaGetSymbolAddress((void**)&p_w2l, g_w2l);

    const int NBLK = (NN + 1023) / 1024;  // 49

    prep_kernel<<<1024, 256>>>(x, W1, W2);
    count_kernel<<<(EE + 255) / 256, 256>>>(ei);
    scan1_kernel<<<NBLK, 1024>>>();
    scan2_kernel<<<1, 64>>>(NBLK);
    scan3_kernel<<<(NN + 255) / 256, 256>>>();
    scatter_kernel<<<(ET + 255) / 256, 256>>>(ei);

    // layer 1: h1 = x @ W1 (+ fused dots)
    {
        dim3 grid(C1 / 128, (NN + 127) / 128);
        mma_gemm_kernel<<<grid, 256>>>(p_xh, p_xl, p_w1h, p_w1l, p_h1b,
                                       a_src1, a_dst1, p_asrc1, p_adst1,
                                       NN, C1, FIN, HEADS);
    }
    agg_kernel<HEADS, HIDC, true><<<NN, HIDC>>>(p_h1b, p_asrc1, p_adst1, b1,
                                                nullptr, p_a1h, p_a1l);

    // layer 2: h2 = act1 @ W2 (+ fused dots)
    {
        dim3 grid(HIDC / 128, (NN + 127) / 128);
        mma_gemm_kernel<<<grid, 256>>>(p_a1h, p_a1l, p_w2h, p_w2l, p_h2b,
                                       a_src2, a_dst2, p_asrc2, p_adst2,
                                       NN, HIDC, C1, 1);
    }
    agg_kernel<1, HIDC, false><<<NN, HIDC>>>(p_h2b, p_asrc2, p_adst2, b2,
                                             p_out2, nullptr, nullptr);

    // pooling + linear head
    pool_kernel<<<((size_t)NN * HIDC + 255) / 256, 256>>>(batch);
    final_kernel<<<GG, HIDC>>>(Wl, bl, out);
}

// round 11
// speedup vs baseline: 2.6270x; 1.0882x over previous
#include <cuda_runtime.h>
#include <cuda_bf16.h>
#include <math.h>
#include <cstdint>

// Problem constants
#define NN    50000
#define EE    800000
#define ET    (EE + NN)      // edges + self loops
#define FIN   128
#define HIDC  128
#define HEADS 4
#define GG    512
#define C1    (HEADS * HIDC) // 512

// ---------------- scratch (static device globals; no allocation allowed) ---
__device__ __nv_bfloat16 g_h1b[(size_t)NN * C1];   // x @ W1 (bf16, gather src)
__device__ __nv_bfloat16 g_h2b[(size_t)NN * HIDC]; // act1 @ W2 (bf16)
__device__ __nv_bfloat16 g_xh[(size_t)NN * FIN];   // x hi
__device__ __nv_bfloat16 g_xl[(size_t)NN * FIN];   // x lo
__device__ __nv_bfloat16 g_a1h[(size_t)NN * C1];   // act1 hi
__device__ __nv_bfloat16 g_a1l[(size_t)NN * C1];   // act1 lo
__device__ __nv_bfloat16 g_w1h[C1 * FIN];    // W1^T [512][128] hi
__device__ __nv_bfloat16 g_w1l[C1 * FIN];
__device__ __nv_bfloat16 g_w2h[HIDC * C1];   // W2^T [128][512] hi
__device__ __nv_bfloat16 g_w2l[HIDC * C1];
__device__ float g_asrc1[NN * HEADS];
__device__ float g_adst1[NN * HEADS];
__device__ float g_asrc2[NN];
__device__ float g_adst2[NN];
__device__ int   g_deg[NN];
__device__ int   g_rowptr[NN + 1];
__device__ int   g_cursor[NN];
__device__ int   g_esrc[ET];
__device__ float g_pool[GG * HIDC];
__device__ float g_cnt[GG];
__device__ int   g_bsum[64];
__device__ int   g_boff[64];

// ====================== helpers ============================================
__device__ __forceinline__ void split_bf16(float v, __nv_bfloat16& h, __nv_bfloat16& l) {
    h = __float2bfloat16_rn(v);
    l = __float2bfloat16_rn(v - __bfloat162float(h));
}

// ---------------- fused init + conversions ---------------------------------
__global__ void prep_kernel(const float* __restrict__ X,
                            const float* __restrict__ W1,
                            const float* __restrict__ W2) {
    int i0 = blockIdx.x * blockDim.x + threadIdx.x;
    int stride = gridDim.x * blockDim.x;
    for (int k = i0; k < NN; k += stride) { g_deg[k] = 1; g_cursor[k] = 0; }
    for (int k = i0; k < GG * HIDC; k += stride) g_pool[k] = 0.f;
    for (int k = i0; k < GG; k += stride) g_cnt[k] = 0.f;
    for (int k = i0; k < NN * FIN / 4; k += stride) {
        int i = k * 4;
        float4 v = *reinterpret_cast<const float4*>(&X[i]);
        __nv_bfloat16 h[4], l[4];
        split_bf16(v.x, h[0], l[0]); split_bf16(v.y, h[1], l[1]);
        split_bf16(v.z, h[2], l[2]); split_bf16(v.w, h[3], l[3]);
        *reinterpret_cast<uint2*>(&g_xh[i]) = *reinterpret_cast<uint2*>(h);
        *reinterpret_cast<uint2*>(&g_xl[i]) = *reinterpret_cast<uint2*>(l);
    }
    for (int k = i0; k < FIN * C1; k += stride) {
        int kk = k / C1, n = k % C1;
        __nv_bfloat16 h, l;
        split_bf16(W1[k], h, l);
        g_w1h[n * FIN + kk] = h;
        g_w1l[n * FIN + kk] = l;
    }
    for (int k = i0; k < C1 * HIDC; k += stride) {
        int kk = k / HIDC, n = k % HIDC;
        __nv_bfloat16 h, l;
        split_bf16(W2[k], h, l);
        g_w2h[n * C1 + kk] = h;
        g_w2l[n * C1 + kk] = l;
    }
}

// ---------------- degree count ---------------------------------------------
__global__ void count_kernel(const int* __restrict__ ei) {
    int i = blockIdx.x * blockDim.x + threadIdx.x;
    if (i < EE) atomicAdd(&g_deg[ei[EE + i]], 1);
}

// ---------------- parallel 3-phase exclusive scan --------------------------
__global__ void scan1_kernel() {
    __shared__ int sm[1024];
    int tid = threadIdx.x;
    int i = blockIdx.x * 1024 + tid;
    int v = (i < NN) ? g_deg[i] : 0;
    sm[tid] = v;
    __syncthreads();
    for (int off = 1; off < 1024; off <<= 1) {
        int tv = (tid >= off) ? sm[tid - off] : 0;
        __syncthreads();
        sm[tid] += tv;
        __syncthreads();
    }
    if (i < NN) g_rowptr[i] = sm[tid] - v;
    if (tid == 1023) g_bsum[blockIdx.x] = sm[1023];
}

__global__ void scan2_kernel(int nblk) {
    __shared__ int sm[64];
    int tid = threadIdx.x;
    int v = (tid < nblk) ? g_bsum[tid] : 0;
    sm[tid] = v;
    __syncthreads();
    for (int off = 1; off < 64; off <<= 1) {
        int tv = (tid >= off) ? sm[tid - off] : 0;
        __syncthreads();
        sm[tid] += tv;
        __syncthreads();
    }
    if (tid < nblk) g_boff[tid] = sm[tid] - v;
    if (tid == 63) g_rowptr[NN] = sm[63];
}

__global__ void scan3_kernel() {
    int i = blockIdx.x * blockDim.x + threadIdx.x;
    if (i < NN) g_rowptr[i] += g_boff[i >> 10];
}

// ---------------- scatter into CSR (edges + self loops) --------------------
__global__ void scatter_kernel(const int* __restrict__ ei) {
    int i = blockIdx.x * blockDim.x + threadIdx.x;
    if (i < EE) {
        int s = ei[i];
        int d = ei[EE + i];
        int pos = g_rowptr[d] + atomicAdd(&g_cursor[d], 1);
        g_esrc[pos] = s;
    } else if (i < ET) {
        int n = i - EE;
        int pos = g_rowptr[n] + atomicAdd(&g_cursor[n], 1);
        g_esrc[pos] = n;
    }
}

// ====================== bf16 mma.sync GEMM + fused dots ====================
#define KC     32
#define APAD   40

__device__ __forceinline__ void mma16816(float* c, const uint32_t* a, const uint32_t* b) {
    asm volatile(
        "mma.sync.aligned.m16n8k16.row.col.f32.bf16.bf16.f32 "
        "{%0,%1,%2,%3}, {%4,%5,%6,%7}, {%8,%9}, {%0,%1,%2,%3};"
        : "+f"(c[0]), "+f"(c[1]), "+f"(c[2]), "+f"(c[3])
        : "r"(a[0]), "r"(a[1]), "r"(a[2]), "r"(a[3]), "r"(b[0]), "r"(b[1]));
}

__global__ __launch_bounds__(256) void mma_gemm_kernel(
    const __nv_bfloat16* __restrict__ Ah, const __nv_bfloat16* __restrict__ Al,
    const __nv_bfloat16* __restrict__ Bth, const __nv_bfloat16* __restrict__ Btl,
    __nv_bfloat16* __restrict__ Cb,
    const float* __restrict__ avs, const float* __restrict__ avd,
    float* __restrict__ asrc_out, float* __restrict__ adst_out,
    int M, int Nn, int K, int H)
{
    __shared__ unsigned short Ahs[128 * APAD];
    __shared__ unsigned short Als[128 * APAD];
    __shared__ unsigned short Bhs[128 * APAD];
    __shared__ unsigned short Bls[128 * APAD];
    __shared__ float s_dt[2][128][2];

    int tid = threadIdx.x;
    int wid = tid >> 5, lane = tid & 31;
    int warp_m = wid & 3;
    int warp_n = wid >> 2;
    int g = lane >> 2, tg = lane & 3;
    int rowBase = blockIdx.y * 128;
    int colBase = blockIdx.x * 128;
    int head = blockIdx.x;

    float acc[2][8][4];
#pragma unroll
    for (int mt = 0; mt < 2; mt++)
#pragma unroll
        for (int nt = 0; nt < 8; nt++)
#pragma unroll
            for (int j = 0; j < 4; j++) acc[mt][nt][j] = 0.f;

    for (int k0 = 0; k0 < K; k0 += KC) {
#pragma unroll
        for (int l = 0; l < 4; l++) {
            int idx = tid + l * 256;
            int row = idx >> 3;
            int q = idx & 7;
            int gr = rowBase + row;
            uint2 vh = make_uint2(0u, 0u), vl = make_uint2(0u, 0u);
            if (gr < M) {
                vh = *reinterpret_cast<const uint2*>(&Ah[(size_t)gr * K + k0 + q * 4]);
                vl = *reinterpret_cast<const uint2*>(&Al[(size_t)gr * K + k0 + q * 4]);
            }
            *reinterpret_cast<uint2*>(&Ahs[row * APAD + q * 4]) = vh;
            *reinterpret_cast<uint2*>(&Als[row * APAD + q * 4]) = vl;
        }
#pragma unroll
        for (int l = 0; l < 4; l++) {
            int idx = tid + l * 256;
            int n = idx >> 3;
            int q = idx & 7;
            uint2 vh = *reinterpret_cast<const uint2*>(&Bth[(size_t)(colBase + n) * K + k0 + q * 4]);
            uint2 vl = *reinterpret_cast<const uint2*>(&Btl[(size_t)(colBase + n) * K + k0 + q * 4]);
            *reinterpret_cast<uint2*>(&Bhs[n * APAD + q * 4]) = vh;
            *reinterpret_cast<uint2*>(&Bls[n * APAD + q * 4]) = vl;
        }
        __syncthreads();

#pragma unroll
        for (int ks = 0; ks < 2; ks++) {
            int kk = ks * 16;
            uint32_t afh[2][4], afl[2][4];
#pragma unroll
            for (int mt = 0; mt < 2; mt++) {
                int r0 = (warp_m * 32 + mt * 16 + g) * APAD + kk + tg * 2;
                int r8 = r0 + 8 * APAD;
                afh[mt][0] = *reinterpret_cast<uint32_t*>(&Ahs[r0]);
                afh[mt][1] = *reinterpret_cast<uint32_t*>(&Ahs[r8]);
                afh[mt][2] = *reinterpret_cast<uint32_t*>(&Ahs[r0 + 8]);
                afh[mt][3] = *reinterpret_cast<uint32_t*>(&Ahs[r8 + 8]);
                afl[mt][0] = *reinterpret_cast<uint32_t*>(&Als[r0]);
                afl[mt][1] = *reinterpret_cast<uint32_t*>(&Als[r8]);
                afl[mt][2] = *reinterpret_cast<uint32_t*>(&Als[r0 + 8]);
                afl[mt][3] = *reinterpret_cast<uint32_t*>(&Als[r8 + 8]);
            }
#pragma unroll
            for (int nt = 0; nt < 8; nt++) {
                int nb = (warp_n * 64 + nt * 8 + g) * APAD + kk + tg * 2;
                uint32_t bfh[2], bfl[2];
                bfh[0] = *reinterpret_cast<uint32_t*>(&Bhs[nb]);
                bfh[1] = *reinterpret_cast<uint32_t*>(&Bhs[nb + 8]);
                bfl[0] = *reinterpret_cast<uint32_t*>(&Bls[nb]);
                bfl[1] = *reinterpret_cast<uint32_t*>(&Bls[nb + 8]);
#pragma unroll
                for (int mt = 0; mt < 2; mt++) {
                    mma16816(acc[mt][nt], afh[mt], bfh);
                    mma16816(acc[mt][nt], afh[mt], bfl);
                    mma16816(acc[mt][nt], afl[mt], bfh);
                }
            }
        }
        __syncthreads();
    }

    // ---- epilogue: bf16 store + fused attention dots ----
    float ps[2][2] = {{0.f, 0.f}, {0.f, 0.f}};
    float pd[2][2] = {{0.f, 0.f}, {0.f, 0.f}};
#pragma unroll
    for (int nt = 0; nt < 8; nt++) {
        int c0 = colBase + warp_n * 64 + nt * 8 + tg * 2;
        float as0 = avs[c0], as1 = avs[c0 + 1];
        float ad0 = avd[c0], ad1 = avd[c0 + 1];
#pragma unroll
        for (int mt = 0; mt < 2; mt++) {
            int r0 = rowBase + warp_m * 32 + mt * 16 + g;
            __nv_bfloat162 v01 = __floats2bfloat162_rn(acc[mt][nt][0], acc[mt][nt][1]);
            __nv_bfloat162 v23 = __floats2bfloat162_rn(acc[mt][nt][2], acc[mt][nt][3]);
            if (r0 < M)
                *reinterpret_cast<__nv_bfloat162*>(&Cb[(size_t)r0 * Nn + c0]) = v01;
            if (r0 + 8 < M)
                *reinterpret_cast<__nv_bfloat162*>(&Cb[(size_t)(r0 + 8) * Nn + c0]) = v23;
            ps[mt][0] += acc[mt][nt][0] * as0 + acc[mt][nt][1] * as1;
            pd[mt][0] += acc[mt][nt][0] * ad0 + acc[mt][nt][1] * ad1;
            ps[mt][1] += acc[mt][nt][2] * as0 + acc[mt][nt][3] * as1;
            pd[mt][1] += acc[mt][nt][2] * ad0 + acc[mt][nt][3] * ad1;
        }
    }
#pragma unroll
    for (int mt = 0; mt < 2; mt++)
#pragma unroll
        for (int hf = 0; hf < 2; hf++) {
            ps[mt][hf] += __shfl_xor_sync(0xffffffffu, ps[mt][hf], 1);
            ps[mt][hf] += __shfl_xor_sync(0xffffffffu, ps[mt][hf], 2);
            pd[mt][hf] += __shfl_xor_sync(0xffffffffu, pd[mt][hf], 1);
            pd[mt][hf] += __shfl_xor_sync(0xffffffffu, pd[mt][hf], 2);
        }
    if (tg == 0) {
#pragma unroll
        for (int mt = 0; mt < 2; mt++)
#pragma unroll
            for (int hf = 0; hf < 2; hf++) {
                int lr = warp_m * 32 + mt * 16 + g + hf * 8;
                s_dt[0][lr][warp_n] = ps[mt][hf];
                s_dt[1][lr][warp_n] = pd[mt][hf];
            }
    }
    __syncthreads();
    if (tid < 128) {
        int grow = rowBase + tid;
        if (grow < M) {
            asrc_out[grow * H + head] = s_dt[0][tid][0] + s_dt[0][tid][1];
            adst_out[grow * H + head] = s_dt[1][tid][0] + s_dt[1][tid][1];
        }
    }
}

// ---------------- agg layer 1: H=4, bf162 pair gather, emit bf16 hi/lo -----
__global__ __launch_bounds__(128) void agg1_kernel(
    const __nv_bfloat16* __restrict__ h,
    const float* __restrict__ asrc, const float* __restrict__ adst,
    const float* __restrict__ bias,
    __nv_bfloat16* __restrict__ outh, __nv_bfloat16* __restrict__ outl)
{
    const int H = HEADS, CH = 64;
    __shared__ int   s_src[CH];
    __shared__ float s_w[CH * H];
    __shared__ float s_f[H];
    __shared__ float s_den[H];

    int node = blockIdx.x, t = threadIdx.x;
    int wid = t >> 5, lane = t & 31;
    int c2 = t & 63;            // channel pair index 0..63
    int hp = t >> 6;            // head pair: heads 2hp, 2hp+1
    int hh0 = hp * 2, hh1 = hp * 2 + 1;
    int beg = g_rowptr[node], end = g_rowptr[node + 1];

    float a0x = 0.f, a0y = 0.f, a1x = 0.f, a1y = 0.f;
    float m = -1e30f, ssum = 0.f;
    float ad = adst[node * H + wid];

    for (int cbeg = beg; cbeg < end; cbeg += CH) {
        int clen = min(CH, end - cbeg);
        {
            float lmax = -1e30f;
            for (int i = lane; i < clen; i += 32) {
                int s = g_esrc[cbeg + i];
                if (wid == 0) s_src[i] = s;
                float l = asrc[s * H + wid] + ad;
                l = l > 0.f ? l : 0.2f * l;
                s_w[i * H + wid] = l;
                lmax = fmaxf(lmax, l);
            }
#pragma unroll
            for (int o = 16; o; o >>= 1)
                lmax = fmaxf(lmax, __shfl_xor_sync(0xffffffffu, lmax, o));
            float newm = fmaxf(m, lmax);
            float f = __expf(m - newm);
            m = newm;
            float lsum = 0.f;
            for (int i = lane; i < clen; i += 32) {
                float w = __expf(s_w[i * H + wid] - m);
                s_w[i * H + wid] = w;
                lsum += w;
            }
#pragma unroll
            for (int o = 16; o; o >>= 1)
                lsum += __shfl_xor_sync(0xffffffffu, lsum, o);
            ssum = ssum * f + lsum;
            if (lane == 0) s_f[wid] = f;
        }
        __syncthreads();
        float f0 = s_f[hh0], f1 = s_f[hh1];
        a0x *= f0; a0y *= f0; a1x *= f1; a1y *= f1;

        int i = 0;
        for (; i + 4 <= clen; i += 4) {
#pragma unroll
            for (int u = 0; u < 4; u++) {
                int s = s_src[i + u];
                const __nv_bfloat162* bp =
                    reinterpret_cast<const __nv_bfloat162*>(h + (size_t)s * C1);
                __nv_bfloat162 va = bp[hh0 * 64 + c2];
                __nv_bfloat162 vb = bp[hh1 * 64 + c2];
                float w0 = s_w[(i + u) * H + hh0];
                float w1 = s_w[(i + u) * H + hh1];
                a0x += w0 * __bfloat162float(va.x);
                a0y += w0 * __bfloat162float(va.y);
                a1x += w1 * __bfloat162float(vb.x);
                a1y += w1 * __bfloat162float(vb.y);
            }
        }
        for (; i < clen; i++) {
            int s = s_src[i];
            const __nv_bfloat162* bp =
                reinterpret_cast<const __nv_bfloat162*>(h + (size_t)s * C1);
            __nv_bfloat162 va = bp[hh0 * 64 + c2];
            __nv_bfloat162 vb = bp[hh1 * 64 + c2];
            float w0 = s_w[i * H + hh0];
            float w1 = s_w[i * H + hh1];
            a0x += w0 * __bfloat162float(va.x);
            a0y += w0 * __bfloat162float(va.y);
            a1x += w1 * __bfloat162float(vb.x);
            a1y += w1 * __bfloat162float(vb.y);
        }
        __syncthreads();
    }
    if (lane == 0) s_den[wid] = ssum;
    __syncthreads();

    float den0 = s_den[hh0], den1 = s_den[hh1];
    int ch0 = hh0 * HIDC + 2 * c2;
    int ch1 = hh1 * HIDC + 2 * c2;
    float v00 = a0x / den0 + bias[ch0];
    float v01 = a0y / den0 + bias[ch0 + 1];
    float v10 = a1x / den1 + bias[ch1];
    float v11 = a1y / den1 + bias[ch1 + 1];
    v00 = v00 > 0.f ? v00 : expm1f(v00);
    v01 = v01 > 0.f ? v01 : expm1f(v01);
    v10 = v10 > 0.f ? v10 : expm1f(v10);
    v11 = v11 > 0.f ? v11 : expm1f(v11);

    __nv_bfloat16 h00, l00, h01, l01, h10, l10, h11, l11;
    split_bf16(v00, h00, l00); split_bf16(v01, h01, l01);
    split_bf16(v10, h10, l10); split_bf16(v11, h11, l11);
    size_t b0 = (size_t)node * C1 + ch0;
    size_t b1 = (size_t)node * C1 + ch1;
    __nv_bfloat162 ph0; ph0.x = h00; ph0.y = h01;
    __nv_bfloat162 pl0; pl0.x = l00; pl0.y = l01;
    __nv_bfloat162 ph1; ph1.x = h10; ph1.y = h11;
    __nv_bfloat162 pl1; pl1.x = l10; pl1.y = l11;
    *reinterpret_cast<__nv_bfloat162*>(&outh[b0]) = ph0;
    *reinterpret_cast<__nv_bfloat162*>(&outl[b0]) = pl0;
    *reinterpret_cast<__nv_bfloat162*>(&outh[b1]) = ph1;
    *reinterpret_cast<__nv_bfloat162*>(&outl[b1]) = pl1;
}

// ---------------- agg layer 2: H=1, fused mean-pool atomics ----------------
__global__ __launch_bounds__(128) void agg2_kernel(
    const __nv_bfloat16* __restrict__ h,
    const float* __restrict__ asrc, const float* __restrict__ adst,
    const float* __restrict__ bias, const int* __restrict__ batch)
{
    const int CH = 64;
    __shared__ int   s_src[CH];
    __shared__ float s_w[CH];
    __shared__ float s_fd[2];       // [0]=f, [1]=den
    __shared__ float s_comb[2][64];

    int node = blockIdx.x, t = threadIdx.x;
    int wid = t >> 5, lane = t & 31;
    int c2 = t & 63;
    int eo = t >> 6;                // edge-offset group 0/1
    int beg = g_rowptr[node], end = g_rowptr[node + 1];

    float acc0 = 0.f, acc1 = 0.f;
    float m = -1e30f, ssum = 0.f;
    float ad = adst[node];

    for (int cbeg = beg; cbeg < end; cbeg += CH) {
        int clen = min(CH, end - cbeg);
        if (wid == 0) {
            float lmax = -1e30f;
            for (int i = lane; i < clen; i += 32) {
                int s = g_esrc[cbeg + i];
                s_src[i] = s;
                float l = asrc[s] + ad;
                l = l > 0.f ? l : 0.2f * l;
                s_w[i] = l;
                lmax = fmaxf(lmax, l);
            }
#pragma unroll
            for (int o = 16; o; o >>= 1)
                lmax = fmaxf(lmax, __shfl_xor_sync(0xffffffffu, lmax, o));
            float newm = fmaxf(m, lmax);
            float f = __expf(m - newm);
            m = newm;
            float lsum = 0.f;
            for (int i = lane; i < clen; i += 32) {
                float w = __expf(s_w[i] - m);
                s_w[i] = w;
                lsum += w;
            }
#pragma unroll
            for (int o = 16; o; o >>= 1)
                lsum += __shfl_xor_sync(0xffffffffu, lsum, o);
            ssum = ssum * f + lsum;
            if (lane == 0) { s_fd[0] = f; s_fd[1] = ssum; }
        }
        __syncthreads();
        float f = s_fd[0];
        acc0 *= f; acc1 *= f;

        int i = eo;
        for (; i + 2 < clen; i += 4) {
            int s0 = s_src[i], s1 = s_src[i + 2];
            float w0 = s_w[i], w1 = s_w[i + 2];
            __nv_bfloat162 v0 =
                reinterpret_cast<const __nv_bfloat162*>(h + (size_t)s0 * HIDC)[c2];
            __nv_bfloat162 v1 =
                reinterpret_cast<const __nv_bfloat162*>(h + (size_t)s1 * HIDC)[c2];
            acc0 += w0 * __bfloat162float(v0.x) + w1 * __bfloat162float(v1.x);
            acc1 += w0 * __bfloat162float(v0.y) + w1 * __bfloat162float(v1.y);
        }
        for (; i < clen; i += 2) {
            int s = s_src[i];
            float w = s_w[i];
            __nv_bfloat162 v =
                reinterpret_cast<const __nv_bfloat162*>(h + (size_t)s * HIDC)[c2];
            acc0 += w * __bfloat162float(v.x);
            acc1 += w * __bfloat162float(v.y);
        }
        __syncthreads();
    }
    if (eo == 1) { s_comb[0][c2] = acc0; s_comb[1][c2] = acc1; }
    __syncthreads();
    int g = batch[node];
    if (eo == 0) {
        float den = s_fd[1];
        float v0 = (acc0 + s_comb[0][c2]) / den + bias[2 * c2];
        float v1 = (acc1 + s_comb[1][c2]) / den + bias[2 * c2 + 1];
        v0 = v0 > 0.f ? v0 : expm1f(v0);
        v1 = v1 > 0.f ? v1 : expm1f(v1);
        atomicAdd(&g_pool[g * HIDC + 2 * c2], v0);
        atomicAdd(&g_pool[g * HIDC + 2 * c2 + 1], v1);
    }
    if (t == 0) atomicAdd(&g_cnt[g], 1.0f);
}

// ---------------- final linear head ----------------------------------------
__global__ void final_kernel(const float* __restrict__ Wl,
                             const float* __restrict__ bl,
                             float* __restrict__ out)
{
    __shared__ float s_red[4];
    int g = blockIdx.x, t = threadIdx.x;
    int lane = t & 31, w = t >> 5;
    float c = fmaxf(g_cnt[g], 1.0f);
    float v = g_pool[g * HIDC + t] / c * Wl[t];
#pragma unroll
    for (int o = 16; o; o >>= 1) v += __shfl_down_sync(0xffffffffu, v, o);
    if (lane == 0) s_red[w] = v;
    __syncthreads();
    if (t == 0) out[g] = s_red[0] + s_red[1] + s_red[2] + s_red[3] + bl[0];
}

// ---------------- launch ----------------------------------------------------
extern "C" void kernel_launch(void* const* d_in, const int* in_sizes, int n_in,
                              void* d_out, int out_size)
{
    const float* x       = (const float*)d_in[0];
    const int*   ei      = (const int*)  d_in[1];
    const int*   batch   = (const int*)  d_in[2];
    const float* W1      = (const float*)d_in[3];
    const float* a_src1  = (const float*)d_in[4];
    const float* a_dst1  = (const float*)d_in[5];
    const float* b1      = (const float*)d_in[6];
    const float* W2      = (const float*)d_in[7];
    const float* a_src2  = (const float*)d_in[8];
    const float* a_dst2  = (const float*)d_in[9];
    const float* b2      = (const float*)d_in[10];
    const float* Wl      = (const float*)d_in[11];
    const float* bl      = (const float*)d_in[12];
    float* out = (float*)d_out;

    float *p_asrc1, *p_adst1, *p_asrc2, *p_adst2;
    __nv_bfloat16 *p_h1b, *p_h2b, *p_xh, *p_xl, *p_a1h, *p_a1l, *p_w1h, *p_w1l, *p_w2h, *p_w2l;
    cudaGetSymbolAddress((void**)&p_h1b,   g_h1b);
    cudaGetSymbolAddress((void**)&p_h2b,   g_h2b);
    cudaGetSymbolAddress((void**)&p_asrc1, g_asrc1);
    cudaGetSymbolAddress((void**)&p_adst1, g_adst1);
    cudaGetSymbolAddress((void**)&p_asrc2, g_asrc2);
    cudaGetSymbolAddress((void**)&p_adst2, g_adst2);
    cudaGetSymbolAddress((void**)&p_xh,  g_xh);
    cudaGetSymbolAddress((void**)&p_xl,  g_xl);
    cudaGetSymbolAddress((void**)&p_a1h, g_a1h);
    cudaGetSymbolAddress((void**)&p_a1l, g_a1l);
    cudaGetSymbolAddress((void**)&p_w1h, g_w1h);
    cudaGetSymbolAddress((void**)&p_w1l, g_w1l);
    cudaGetSymbolAddress((void**)&p_w2h, g_w2h);
    cudaGetSymbolAddress((void**)&p_w2l, g_w2l);

    const int NBLK = (NN + 1023) / 1024;  // 49

    prep_kernel<<<1024, 256>>>(x, W1, W2);
    count_kernel<<<(EE + 255) / 256, 256>>>(ei);
    scan1_kernel<<<NBLK, 1024>>>();
    scan2_kernel<<<1, 64>>>(NBLK);
    scan3_kernel<<<(NN + 255) / 256, 256>>>();
    scatter_kernel<<<(ET + 255) / 256, 256>>>(ei);

    // layer 1: h1 = x @ W1 (+ fused dots)
    {
        dim3 grid(C1 / 128, (NN + 127) / 128);
        mma_gemm_kernel<<<grid, 256>>>(p_xh, p_xl, p_w1h, p_w1l, p_h1b,
                                       a_src1, a_dst1, p_asrc1, p_adst1,
                                       NN, C1, FIN, HEADS);
    }
    agg1_kernel<<<NN, 128>>>(p_h1b, p_asrc1, p_adst1, b1, p_a1h, p_a1l);

    // layer 2: h2 = act1 @ W2 (+ fused dots)
    {
        dim3 grid(HIDC / 128, (NN + 127) / 128);
        mma_gemm_kernel<<<grid, 256>>>(p_a1h, p_a1l, p_w2h, p_w2l, p_h2b,
                                       a_src2, a_dst2, p_asrc2, p_adst2,
                                       NN, HIDC, C1, 1);
    }
    // layer 2 agg + fused mean-pool
    agg2_kernel<<<NN, 128>>>(p_h2b, p_asrc2, p_adst2, b2, batch);

    final_kernel<<<GG, HIDC>>>(Wl, bl, out);
}

// round 12
// speedup vs baseline: 3.0198x; 1.1495x over previous
#include <cuda_runtime.h>
#include <cuda_bf16.h>
#include <math.h>
#include <cstdint>

// Problem constants
#define NN    50000
#define EE    800000
#define ET    (EE + NN)      // edges + self loops
#define FIN   128
#define HIDC  128
#define HEADS 4
#define GG    512
#define C1    (HEADS * HIDC) // 512

// ---------------- scratch (static device globals; no allocation allowed) ---
__device__ __nv_bfloat16 g_h1b[(size_t)NN * C1];   // x @ W1 (bf16, gather src)
__device__ __nv_bfloat16 g_h2b[(size_t)NN * HIDC]; // act1 @ W2 (bf16)
__device__ __nv_bfloat16 g_xh[(size_t)NN * FIN];   // x (bf16)
__device__ __nv_bfloat16 g_a1h[(size_t)NN * C1];   // act1 (bf16)
__device__ __nv_bfloat16 g_w1h[C1 * FIN];    // W1^T [512][128] hi
__device__ __nv_bfloat16 g_w1l[C1 * FIN];    // W1^T lo
__device__ __nv_bfloat16 g_w2h[HIDC * C1];   // W2^T [128][512] hi
__device__ __nv_bfloat16 g_w2l[HIDC * C1];   // W2^T lo
__device__ float g_asrc1[NN * HEADS];
__device__ float g_adst1[NN * HEADS];
__device__ float g_asrc2[NN];
__device__ float g_adst2[NN];
__device__ int   g_deg[NN];
__device__ int   g_rowptr[NN + 1];
__device__ int   g_cursor[NN];
__device__ int   g_esrc[ET];
__device__ float g_pool[GG * HIDC];
__device__ float g_cnt[GG];
__device__ int   g_bsum[64];
__device__ int   g_boff[64];

// ====================== helpers ============================================
__device__ __forceinline__ void split_bf16(float v, __nv_bfloat16& h, __nv_bfloat16& l) {
    h = __float2bfloat16_rn(v);
    l = __float2bfloat16_rn(v - __bfloat162float(h));
}

// ---------------- fused init + conversions ---------------------------------
__global__ void prep_kernel(const float* __restrict__ X,
                            const float* __restrict__ W1,
                            const float* __restrict__ W2) {
    int i0 = blockIdx.x * blockDim.x + threadIdx.x;
    int stride = gridDim.x * blockDim.x;
    for (int k = i0; k < NN; k += stride) { g_deg[k] = 1; g_cursor[k] = 0; }
    for (int k = i0; k < GG * HIDC; k += stride) g_pool[k] = 0.f;
    for (int k = i0; k < GG; k += stride) g_cnt[k] = 0.f;
    for (int k = i0; k < NN * FIN / 4; k += stride) {
        int i = k * 4;
        float4 v = *reinterpret_cast<const float4*>(&X[i]);
        __nv_bfloat16 h[4];
        h[0] = __float2bfloat16_rn(v.x); h[1] = __float2bfloat16_rn(v.y);
        h[2] = __float2bfloat16_rn(v.z); h[3] = __float2bfloat16_rn(v.w);
        *reinterpret_cast<uint2*>(&g_xh[i]) = *reinterpret_cast<uint2*>(h);
    }
    for (int k = i0; k < FIN * C1; k += stride) {
        int kk = k / C1, n = k % C1;
        __nv_bfloat16 h, l;
        split_bf16(W1[k], h, l);
        g_w1h[n * FIN + kk] = h;
        g_w1l[n * FIN + kk] = l;
    }
    for (int k = i0; k < C1 * HIDC; k += stride) {
        int kk = k / HIDC, n = k % HIDC;
        __nv_bfloat16 h, l;
        split_bf16(W2[k], h, l);
        g_w2h[n * C1 + kk] = h;
        g_w2l[n * C1 + kk] = l;
    }
}

// ---------------- degree count ---------------------------------------------
__global__ void count_kernel(const int* __restrict__ ei) {
    int i = blockIdx.x * blockDim.x + threadIdx.x;
    if (i < EE) atomicAdd(&g_deg[ei[EE + i]], 1);
}

// ---------------- parallel 3-phase exclusive scan --------------------------
__global__ void scan1_kernel() {
    __shared__ int sm[1024];
    int tid = threadIdx.x;
    int i = blockIdx.x * 1024 + tid;
    int v = (i < NN) ? g_deg[i] : 0;
    sm[tid] = v;
    __syncthreads();
    for (int off = 1; off < 1024; off <<= 1) {
        int tv = (tid >= off) ? sm[tid - off] : 0;
        __syncthreads();
        sm[tid] += tv;
        __syncthreads();
    }
    if (i < NN) g_rowptr[i] = sm[tid] - v;
    if (tid == 1023) g_bsum[blockIdx.x] = sm[1023];
}

__global__ void scan2_kernel(int nblk) {
    __shared__ int sm[64];
    int tid = threadIdx.x;
    int v = (tid < nblk) ? g_bsum[tid] : 0;
    sm[tid] = v;
    __syncthreads();
    for (int off = 1; off < 64; off <<= 1) {
        int tv = (tid >= off) ? sm[tid - off] : 0;
        __syncthreads();
        sm[tid] += tv;
        __syncthreads();
    }
    if (tid < nblk) g_boff[tid] = sm[tid] - v;
    if (tid == 63) g_rowptr[NN] = sm[63];
}

__global__ void scan3_kernel() {
    int i = blockIdx.x * blockDim.x + threadIdx.x;
    if (i < NN) g_rowptr[i] += g_boff[i >> 10];
}

// ---------------- scatter into CSR (edges + self loops) --------------------
__global__ void scatter_kernel(const int* __restrict__ ei) {
    int i = blockIdx.x * blockDim.x + threadIdx.x;
    if (i < EE) {
        int s = ei[i];
        int d = ei[EE + i];
        int pos = g_rowptr[d] + atomicAdd(&g_cursor[d], 1);
        g_esrc[pos] = s;
    } else if (i < ET) {
        int n = i - EE;
        int pos = g_rowptr[n] + atomicAdd(&g_cursor[n], 1);
        g_esrc[pos] = n;
    }
}

// ====================== bf16 mma.sync GEMM + fused dots ====================
// C = A @ B with A bf16 (activations, rounded once), B bf16 hi/lo (weights).
// 2 accumulating MMAs per product: A*Bh + A*Bl.
#define KC     32
#define APAD   40

__device__ __forceinline__ void mma16816(float* c, const uint32_t* a, const uint32_t* b) {
    asm volatile(
        "mma.sync.aligned.m16n8k16.row.col.f32.bf16.bf16.f32 "
        "{%0,%1,%2,%3}, {%4,%5,%6,%7}, {%8,%9}, {%0,%1,%2,%3};"
        : "+f"(c[0]), "+f"(c[1]), "+f"(c[2]), "+f"(c[3])
        : "r"(a[0]), "r"(a[1]), "r"(a[2]), "r"(a[3]), "r"(b[0]), "r"(b[1]));
}

__global__ __launch_bounds__(256) void mma_gemm_kernel(
    const __nv_bfloat16* __restrict__ Ah,
    const __nv_bfloat16* __restrict__ Bth, const __nv_bfloat16* __restrict__ Btl,
    __nv_bfloat16* __restrict__ Cb,
    const float* __restrict__ avs, const float* __restrict__ avd,
    float* __restrict__ asrc_out, float* __restrict__ adst_out,
    int M, int Nn, int K, int H)
{
    __shared__ unsigned short Ahs[128 * APAD];
    __shared__ unsigned short Bhs[128 * APAD];
    __shared__ unsigned short Bls[128 * APAD];
    __shared__ float s_dt[2][128][2];

    int tid = threadIdx.x;
    int wid = tid >> 5, lane = tid & 31;
    int warp_m = wid & 3;
    int warp_n = wid >> 2;
    int g = lane >> 2, tg = lane & 3;
    int rowBase = blockIdx.y * 128;
    int colBase = blockIdx.x * 128;
    int head = blockIdx.x;

    float acc[2][8][4];
#pragma unroll
    for (int mt = 0; mt < 2; mt++)
#pragma unroll
        for (int nt = 0; nt < 8; nt++)
#pragma unroll
            for (int j = 0; j < 4; j++) acc[mt][nt][j] = 0.f;

    for (int k0 = 0; k0 < K; k0 += KC) {
        // A tile: 128 rows x 32 k (bf16 only)
#pragma unroll
        for (int l = 0; l < 2; l++) {
            int idx = tid + l * 256;          // 0..511 : 128 rows x 4 uint2
            int row = idx >> 2;
            int q = idx & 3;                  // uint2 covers 8 halves? no: 4 halves
            // each uint2 = 4 bf16; need 8 per row (32 k): use 2 loads of uint4
            (void)row; (void)q;
        }
        // simpler: 1024 uint2-of-4-halves slots = 128 rows * 8
#pragma unroll
        for (int l = 0; l < 4; l++) {
            int idx = tid + l * 256;          // 0..1023
            int row = idx >> 3;
            int q = idx & 7;
            int gr = rowBase + row;
            uint2 vh = make_uint2(0u, 0u);
            if (gr < M)
                vh = *reinterpret_cast<const uint2*>(&Ah[(size_t)gr * K + k0 + q * 4]);
            *reinterpret_cast<uint2*>(&Ahs[row * APAD + q * 4]) = vh;
        }
        // B tiles hi/lo
#pragma unroll
        for (int l = 0; l < 4; l++) {
            int idx = tid + l * 256;
            int n = idx >> 3;
            int q = idx & 7;
            uint2 vh = *reinterpret_cast<const uint2*>(&Bth[(size_t)(colBase + n) * K + k0 + q * 4]);
            uint2 vl = *reinterpret_cast<const uint2*>(&Btl[(size_t)(colBase + n) * K + k0 + q * 4]);
            *reinterpret_cast<uint2*>(&Bhs[n * APAD + q * 4]) = vh;
            *reinterpret_cast<uint2*>(&Bls[n * APAD + q * 4]) = vl;
        }
        __syncthreads();

#pragma unroll
        for (int ks = 0; ks < 2; ks++) {
            int kk = ks * 16;
            uint32_t afh[2][4];
#pragma unroll
            for (int mt = 0; mt < 2; mt++) {
                int r0 = (warp_m * 32 + mt * 16 + g) * APAD + kk + tg * 2;
                int r8 = r0 + 8 * APAD;
                afh[mt][0] = *reinterpret_cast<uint32_t*>(&Ahs[r0]);
                afh[mt][1] = *reinterpret_cast<uint32_t*>(&Ahs[r8]);
                afh[mt][2] = *reinterpret_cast<uint32_t*>(&Ahs[r0 + 8]);
                afh[mt][3] = *reinterpret_cast<uint32_t*>(&Ahs[r8 + 8]);
            }
#pragma unroll
            for (int nt = 0; nt < 8; nt++) {
                int nb = (warp_n * 64 + nt * 8 + g) * APAD + kk + tg * 2;
                uint32_t bfh[2], bfl[2];
                bfh[0] = *reinterpret_cast<uint32_t*>(&Bhs[nb]);
                bfh[1] = *reinterpret_cast<uint32_t*>(&Bhs[nb + 8]);
                bfl[0] = *reinterpret_cast<uint32_t*>(&Bls[nb]);
                bfl[1] = *reinterpret_cast<uint32_t*>(&Bls[nb + 8]);
#pragma unroll
                for (int mt = 0; mt < 2; mt++) {
                    mma16816(acc[mt][nt], afh[mt], bfh);
                    mma16816(acc[mt][nt], afh[mt], bfl);
                }
            }
        }
        __syncthreads();
    }

    // ---- epilogue: bf16 store + fused attention dots ----
    float ps[2][2] = {{0.f, 0.f}, {0.f, 0.f}};
    float pd[2][2] = {{0.f, 0.f}, {0.f, 0.f}};
#pragma unroll
    for (int nt = 0; nt < 8; nt++) {
        int c0 = colBase + warp_n * 64 + nt * 8 + tg * 2;
        float as0 = avs[c0], as1 = avs[c0 + 1];
        float ad0 = avd[c0], ad1 = avd[c0 + 1];
#pragma unroll
        for (int mt = 0; mt < 2; mt++) {
            int r0 = rowBase + warp_m * 32 + mt * 16 + g;
            __nv_bfloat162 v01 = __floats2bfloat162_rn(acc[mt][nt][0], acc[mt][nt][1]);
            __nv_bfloat162 v23 = __floats2bfloat162_rn(acc[mt][nt][2], acc[mt][nt][3]);
            if (r0 < M)
                *reinterpret_cast<__nv_bfloat162*>(&Cb[(size_t)r0 * Nn + c0]) = v01;
            if (r0 + 8 < M)
                *reinterpret_cast<__nv_bfloat162*>(&Cb[(size_t)(r0 + 8) * Nn + c0]) = v23;
            ps[mt][0] += acc[mt][nt][0] * as0 + acc[mt][nt][1] * as1;
            pd[mt][0] += acc[mt][nt][0] * ad0 + acc[mt][nt][1] * ad1;
            ps[mt][1] += acc[mt][nt][2] * as0 + acc[mt][nt][3] * as1;
            pd[mt][1] += acc[mt][nt][2] * ad0 + acc[mt][nt][3] * ad1;
        }
    }
#pragma unroll
    for (int mt = 0; mt < 2; mt++)
#pragma unroll
        for (int hf = 0; hf < 2; hf++) {
            ps[mt][hf] += __shfl_xor_sync(0xffffffffu, ps[mt][hf], 1);
            ps[mt][hf] += __shfl_xor_sync(0xffffffffu, ps[mt][hf], 2);
            pd[mt][hf] += __shfl_xor_sync(0xffffffffu, pd[mt][hf], 1);
            pd[mt][hf] += __shfl_xor_sync(0xffffffffu, pd[mt][hf], 2);
        }
    if (tg == 0) {
#pragma unroll
        for (int mt = 0; mt < 2; mt++)
#pragma unroll
            for (int hf = 0; hf < 2; hf++) {
                int lr = warp_m * 32 + mt * 16 + g + hf * 8;
                s_dt[0][lr][warp_n] = ps[mt][hf];
                s_dt[1][lr][warp_n] = pd[mt][hf];
            }
    }
    __syncthreads();
    if (tid < 128) {
        int grow = rowBase + tid;
        if (grow < M) {
            asrc_out[grow * H + head] = s_dt[0][tid][0] + s_dt[0][tid][1];
            adst_out[grow * H + head] = s_dt[1][tid][0] + s_dt[1][tid][1];
        }
    }
}

// ---------------- agg layer 1: H=4, bf162 pair gather, emit bf16 -----------
__global__ __launch_bounds__(128) void agg1_kernel(
    const __nv_bfloat16* __restrict__ h,
    const float* __restrict__ asrc, const float* __restrict__ adst,
    const float* __restrict__ bias,
    __nv_bfloat16* __restrict__ outh)
{
    const int H = HEADS, CH = 64;
    __shared__ int   s_src[CH];
    __shared__ float s_w[CH * H];
    __shared__ float s_f[H];
    __shared__ float s_den[H];

    int node = blockIdx.x, t = threadIdx.x;
    int wid = t >> 5, lane = t & 31;
    int c2 = t & 63;            // channel pair index 0..63
    int hp = t >> 6;            // head pair: heads 2hp, 2hp+1
    int hh0 = hp * 2, hh1 = hp * 2 + 1;
    int beg = g_rowptr[node], end = g_rowptr[node + 1];

    float a0x = 0.f, a0y = 0.f, a1x = 0.f, a1y = 0.f;
    float m = -1e30f, ssum = 0.f;
    float ad = adst[node * H + wid];

    for (int cbeg = beg; cbeg < end; cbeg += CH) {
        int clen = min(CH, end - cbeg);
        {
            float lmax = -1e30f;
            for (int i = lane; i < clen; i += 32) {
                int s = g_esrc[cbeg + i];
                if (wid == 0) s_src[i] = s;
                float l = asrc[s * H + wid] + ad;
                l = l > 0.f ? l : 0.2f * l;
                s_w[i * H + wid] = l;
                lmax = fmaxf(lmax, l);
            }
#pragma unroll
            for (int o = 16; o; o >>= 1)
                lmax = fmaxf(lmax, __shfl_xor_sync(0xffffffffu, lmax, o));
            float newm = fmaxf(m, lmax);
            float f = __expf(m - newm);
            m = newm;
            float lsum = 0.f;
            for (int i = lane; i < clen; i += 32) {
                float w = __expf(s_w[i * H + wid] - m);
                s_w[i * H + wid] = w;
                lsum += w;
            }
#pragma unroll
            for (int o = 16; o; o >>= 1)
                lsum += __shfl_xor_sync(0xffffffffu, lsum, o);
            ssum = ssum * f + lsum;
            if (lane == 0) s_f[wid] = f;
        }
        __syncthreads();
        float f0 = s_f[hh0], f1 = s_f[hh1];
        a0x *= f0; a0y *= f0; a1x *= f1; a1y *= f1;

        int i = 0;
        for (; i + 4 <= clen; i += 4) {
#pragma unroll
            for (int u = 0; u < 4; u++) {
                int s = s_src[i + u];
                const __nv_bfloat162* bp =
                    reinterpret_cast<const __nv_bfloat162*>(h + (size_t)s * C1);
                __nv_bfloat162 va = bp[hh0 * 64 + c2];
                __nv_bfloat162 vb = bp[hh1 * 64 + c2];
                float w0 = s_w[(i + u) * H + hh0];
                float w1 = s_w[(i + u) * H + hh1];
                a0x += w0 * __bfloat162float(va.x);
                a0y += w0 * __bfloat162float(va.y);
                a1x += w1 * __bfloat162float(vb.x);
                a1y += w1 * __bfloat162float(vb.y);
            }
        }
        for (; i < clen; i++) {
            int s = s_src[i];
            const __nv_bfloat162* bp =
                reinterpret_cast<const __nv_bfloat162*>(h + (size_t)s * C1);
            __nv_bfloat162 va = bp[hh0 * 64 + c2];
            __nv_bfloat162 vb = bp[hh1 * 64 + c2];
            float w0 = s_w[i * H + hh0];
            float w1 = s_w[i * H + hh1];
            a0x += w0 * __bfloat162float(va.x);
            a0y += w0 * __bfloat162float(va.y);
            a1x += w1 * __bfloat162float(vb.x);
            a1y += w1 * __bfloat162float(vb.y);
        }
        __syncthreads();
    }
    if (lane == 0) s_den[wid] = ssum;
    __syncthreads();

    float den0 = s_den[hh0], den1 = s_den[hh1];
    int ch0 = hh0 * HIDC + 2 * c2;
    int ch1 = hh1 * HIDC + 2 * c2;
    float v00 = a0x / den0 + bias[ch0];
    float v01 = a0y / den0 + bias[ch0 + 1];
    float v10 = a1x / den1 + bias[ch1];
    float v11 = a1y / den1 + bias[ch1 + 1];
    v00 = v00 > 0.f ? v00 : expm1f(v00);
    v01 = v01 > 0.f ? v01 : expm1f(v01);
    v10 = v10 > 0.f ? v10 : expm1f(v10);
    v11 = v11 > 0.f ? v11 : expm1f(v11);

    size_t b0 = (size_t)node * C1 + ch0;
    size_t b1 = (size_t)node * C1 + ch1;
    *reinterpret_cast<__nv_bfloat162*>(&outh[b0]) = __floats2bfloat162_rn(v00, v01);
    *reinterpret_cast<__nv_bfloat162*>(&outh[b1]) = __floats2bfloat162_rn(v10, v11);
}

// ---------------- agg layer 2: H=1, fused mean-pool atomics ----------------
__global__ __launch_bounds__(128) void agg2_kernel(
    const __nv_bfloat16* __restrict__ h,
    const float* __restrict__ asrc, const float* __restrict__ adst,
    const float* __restrict__ bias, const int* __restrict__ batch)
{
    const int CH = 64;
    __shared__ int   s_src[CH];
    __shared__ float s_w[CH];
    __shared__ float s_fd[2];       // [0]=f, [1]=den
    __shared__ float s_comb[2][64];

    int node = blockIdx.x, t = threadIdx.x;
    int wid = t >> 5, lane = t & 31;
    int c2 = t & 63;
    int eo = t >> 6;                // edge-offset group 0/1
    int beg = g_rowptr[node], end = g_rowptr[node + 1];

    float acc0 = 0.f, acc1 = 0.f;
    float m = -1e30f, ssum = 0.f;
    float ad = adst[node];

    for (int cbeg = beg; cbeg < end; cbeg += CH) {
        int clen = min(CH, end - cbeg);
        if (wid == 0) {
            float lmax = -1e30f;
            for (int i = lane; i < clen; i += 32) {
                int s = g_esrc[cbeg + i];
                s_src[i] = s;
                float l = asrc[s] + ad;
                l = l > 0.f ? l : 0.2f * l;
                s_w[i] = l;
                lmax = fmaxf(lmax, l);
            }
#pragma unroll
            for (int o = 16; o; o >>= 1)
                lmax = fmaxf(lmax, __shfl_xor_sync(0xffffffffu, lmax, o));
            float newm = fmaxf(m, lmax);
            float f = __expf(m - newm);
            m = newm;
            float lsum = 0.f;
            for (int i = lane; i < clen; i += 32) {
                float w = __expf(s_w[i] - m);
                s_w[i] = w;
                lsum += w;
            }
#pragma unroll
            for (int o = 16; o; o >>= 1)
                lsum += __shfl_xor_sync(0xffffffffu, lsum, o);
            ssum = ssum * f + lsum;
            if (lane == 0) { s_fd[0] = f; s_fd[1] = ssum; }
        }
        __syncthreads();
        float f = s_fd[0];
        acc0 *= f; acc1 *= f;

        int i = eo;
        for (; i + 2 < clen; i += 4) {
            int s0 = s_src[i], s1 = s_src[i + 2];
            float w0 = s_w[i], w1 = s_w[i + 2];
            __nv_bfloat162 v0 =
                reinterpret_cast<const __nv_bfloat162*>(h + (size_t)s0 * HIDC)[c2];
            __nv_bfloat162 v1 =
                reinterpret_cast<const __nv_bfloat162*>(h + (size_t)s1 * HIDC)[c2];
            acc0 += w0 * __bfloat162float(v0.x) + w1 * __bfloat162float(v1.x);
            acc1 += w0 * __bfloat162float(v0.y) + w1 * __bfloat162float(v1.y);
        }
        for (; i < clen; i += 2) {
            int s = s_src[i];
            float w = s_w[i];
            __nv_bfloat162 v =
                reinterpret_cast<const __nv_bfloat162*>(h + (size_t)s * HIDC)[c2];
            acc0 += w * __bfloat162float(v.x);
            acc1 += w * __bfloat162float(v.y);
        }
        __syncthreads();
    }
    if (eo == 1) { s_comb[0][c2] = acc0; s_comb[1][c2] = acc1; }
    __syncthreads();
    int g = batch[node];
    if (eo == 0) {
        float den = s_fd[1];
        float v0 = (acc0 + s_comb[0][c2]) / den + bias[2 * c2];
        float v1 = (acc1 + s_comb[1][c2]) / den + bias[2 * c2 + 1];
        v0 = v0 > 0.f ? v0 : expm1f(v0);
        v1 = v1 > 0.f ? v1 : expm1f(v1);
        atomicAdd(&g_pool[g * HIDC + 2 * c2], v0);
        atomicAdd(&g_pool[g * HIDC + 2 * c2 + 1], v1);
    }
    if (t == 0) atomicAdd(&g_cnt[g], 1.0f);
}

// ---------------- final linear head ----------------------------------------
__global__ void final_kernel(const float* __restrict__ Wl,
                             const float* __restrict__ bl,
                             float* __restrict__ out)
{
    __shared__ float s_red[4];
    int g = blockIdx.x, t = threadIdx.x;
    int lane = t & 31, w = t >> 5;
    float c = fmaxf(g_cnt[g], 1.0f);
    float v = g_pool[g * HIDC + t] / c * Wl[t];
#pragma unroll
    for (int o = 16; o; o >>= 1) v += __shfl_down_sync(0xffffffffu, v, o);
    if (lane == 0) s_red[w] = v;
    __syncthreads();
    if (t == 0) out[g] = s_red[0] + s_red[1] + s_red[2] + s_red[3] + bl[0];
}

// ---------------- launch ----------------------------------------------------
extern "C" void kernel_launch(void* const* d_in, const int* in_sizes, int n_in,
                              void* d_out, int out_size)
{
    const float* x       = (const float*)d_in[0];
    const int*   ei      = (const int*)  d_in[1];
    const int*   batch   = (const int*)  d_in[2];
    const float* W1      = (const float*)d_in[3];
    const float* a_src1  = (const float*)d_in[4];
    const float* a_dst1  = (const float*)d_in[5];
    const float* b1      = (const float*)d_in[6];
    const float* W2      = (const float*)d_in[7];
    const float* a_src2  = (const float*)d_in[8];
    const float* a_dst2  = (const float*)d_in[9];
    const float* b2      = (const float*)d_in[10];
    const float* Wl      = (const float*)d_in[11];
    const float* bl      = (const float*)d_in[12];
    float* out = (float*)d_out;

    float *p_asrc1, *p_adst1, *p_asrc2, *p_adst2;
    __nv_bfloat16 *p_h1b, *p_h2b, *p_xh, *p_a1h, *p_w1h, *p_w1l, *p_w2h, *p_w2l;
    cudaGetSymbolAddress((void**)&p_h1b,   g_h1b);
    cudaGetSymbolAddress((void**)&p_h2b,   g_h2b);
    cudaGetSymbolAddress((void**)&p_asrc1, g_asrc1);
    cudaGetSymbolAddress((void**)&p_adst1, g_adst1);
    cudaGetSymbolAddress((void**)&p_asrc2, g_asrc2);
    cudaGetSymbolAddress((void**)&p_adst2, g_adst2);
    cudaGetSymbolAddress((void**)&p_xh,  g_xh);
    cudaGetSymbolAddress((void**)&p_a1h, g_a1h);
    cudaGetSymbolAddress((void**)&p_w1h, g_w1h);
    cudaGetSymbolAddress((void**)&p_w1l, g_w1l);
    cudaGetSymbolAddress((void**)&p_w2h, g_w2h);
    cudaGetSymbolAddress((void**)&p_w2l, g_w2l);

    const int NBLK = (NN + 1023) / 1024;  // 49

    prep_kernel<<<1024, 256>>>(x, W1, W2);
    count_kernel<<<(EE + 255) / 256, 256>>>(ei);
    scan1_kernel<<<NBLK, 1024>>>();
    scan2_kernel<<<1, 64>>>(NBLK);
    scan3_kernel<<<(NN + 255) / 256, 256>>>();
    scatter_kernel<<<(ET + 255) / 256, 256>>>(ei);

    // layer 1: h1 = x @ W1 (+ fused dots)
    {
        dim3 grid(C1 / 128, (NN + 127) / 128);
        mma_gemm_kernel<<<grid, 256>>>(p_xh, p_w1h, p_w1l, p_h1b,
                                       a_src1, a_dst1, p_asrc1, p_adst1,
                                       NN, C1, FIN, HEADS);
    }
    agg1_kernel<<<NN, 128>>>(p_h1b, p_asrc1, p_adst1, b1, p_a1h);

    // layer 2: h2 = act1 @ W2 (+ fused dots)
    {
        dim3 grid(HIDC / 128, (NN + 127) / 128);
        mma_gemm_kernel<<<grid, 256>>>(p_a1h, p_w2h, p_w2l, p_h2b,
                                       a_src2, a_dst2, p_asrc2, p_adst2,
                                       NN, HIDC, C1, 1);
    }
    // layer 2 agg + fused mean-pool
    agg2_kernel<<<NN, 128>>>(p_h2b, p_asrc2, p_adst2, b2, batch);

    final_kernel<<<GG, HIDC>>>(Wl, bl, out);
}

// round 13
// speedup vs baseline: 3.1303x; 1.0366x over previous
#include <cuda_runtime.h>
#include <cuda_bf16.h>
#include <math.h>
#include <cstdint>

// Problem constants
#define NN    50000
#define EE    800000
#define ET    (EE + NN)      // edges + self loops
#define FIN   128
#define HIDC  128
#define HEADS 4
#define GG    512
#define C1    (HEADS * HIDC) // 512

// ---------------- scratch (static device globals; no allocation allowed) ---
__device__ __nv_bfloat16 g_h1b[(size_t)NN * C1];   // x @ W1 (bf16, gather src)
__device__ __nv_bfloat16 g_h2b[(size_t)NN * HIDC]; // act1 @ W2 (bf16)
__device__ __nv_bfloat16 g_xh[(size_t)NN * FIN];   // x (bf16)
__device__ __nv_bfloat16 g_a1h[(size_t)NN * C1];   // act1 (bf16)
__device__ __nv_bfloat16 g_w1h[C1 * FIN];    // W1^T [512][128] hi
__device__ __nv_bfloat16 g_w1l[C1 * FIN];    // W1^T lo
__device__ __nv_bfloat16 g_w2h[HIDC * C1];   // W2^T [128][512] hi
__device__ __nv_bfloat16 g_w2l[HIDC * C1];   // W2^T lo
__device__ float g_asrc1[NN * HEADS];
__device__ float g_adst1[NN * HEADS];
__device__ float g_asrc2[NN];
__device__ float g_adst2[NN];
__device__ int   g_deg[NN];
__device__ int   g_rowptr[NN + 1];
__device__ int   g_cursor[NN];
__device__ int   g_esrc[ET];
__device__ float g_pool[GG * HIDC];
__device__ float g_cnt[GG];
__device__ int   g_bsum[64];
__device__ int   g_boff[64];

// ====================== helpers ============================================
__device__ __forceinline__ void split_bf16(float v, __nv_bfloat16& h, __nv_bfloat16& l) {
    h = __float2bfloat16_rn(v);
    l = __float2bfloat16_rn(v - __bfloat162float(h));
}

// ---------------- fused init + conversions ---------------------------------
__global__ void prep_kernel(const float* __restrict__ X,
                            const float* __restrict__ W1,
                            const float* __restrict__ W2) {
    int i0 = blockIdx.x * blockDim.x + threadIdx.x;
    int stride = gridDim.x * blockDim.x;
    for (int k = i0; k < NN; k += stride) { g_deg[k] = 1; g_cursor[k] = 0; }
    for (int k = i0; k < GG * HIDC; k += stride) g_pool[k] = 0.f;
    for (int k = i0; k < GG; k += stride) g_cnt[k] = 0.f;
    for (int k = i0; k < NN * FIN / 4; k += stride) {
        int i = k * 4;
        float4 v = *reinterpret_cast<const float4*>(&X[i]);
        __nv_bfloat16 h[4];
        h[0] = __float2bfloat16_rn(v.x); h[1] = __float2bfloat16_rn(v.y);
        h[2] = __float2bfloat16_rn(v.z); h[3] = __float2bfloat16_rn(v.w);
        *reinterpret_cast<uint2*>(&g_xh[i]) = *reinterpret_cast<uint2*>(h);
    }
    for (int k = i0; k < FIN * C1; k += stride) {
        int kk = k / C1, n = k % C1;
        __nv_bfloat16 h, l;
        split_bf16(W1[k], h, l);
        g_w1h[n * FIN + kk] = h;
        g_w1l[n * FIN + kk] = l;
    }
    for (int k = i0; k < C1 * HIDC; k += stride) {
        int kk = k / HIDC, n = k % HIDC;
        __nv_bfloat16 h, l;
        split_bf16(W2[k], h, l);
        g_w2h[n * C1 + kk] = h;
        g_w2l[n * C1 + kk] = l;
    }
}

// ---------------- degree count ---------------------------------------------
__global__ void count_kernel(const int* __restrict__ ei) {
    int i = blockIdx.x * blockDim.x + threadIdx.x;
    if (i < EE) atomicAdd(&g_deg[ei[EE + i]], 1);
}

// ---------------- parallel 3-phase exclusive scan --------------------------
__global__ void scan1_kernel() {
    __shared__ int sm[1024];
    int tid = threadIdx.x;
    int i = blockIdx.x * 1024 + tid;
    int v = (i < NN) ? g_deg[i] : 0;
    sm[tid] = v;
    __syncthreads();
    for (int off = 1; off < 1024; off <<= 1) {
        int tv = (tid >= off) ? sm[tid - off] : 0;
        __syncthreads();
        sm[tid] += tv;
        __syncthreads();
    }
    if (i < NN) g_rowptr[i] = sm[tid] - v;
    if (tid == 1023) g_bsum[blockIdx.x] = sm[1023];
}

__global__ void scan2_kernel(int nblk) {
    __shared__ int sm[64];
    int tid = threadIdx.x;
    int v = (tid < nblk) ? g_bsum[tid] : 0;
    sm[tid] = v;
    __syncthreads();
    for (int off = 1; off < 64; off <<= 1) {
        int tv = (tid >= off) ? sm[tid - off] : 0;
        __syncthreads();
        sm[tid] += tv;
        __syncthreads();
    }
    if (tid < nblk) g_boff[tid] = sm[tid] - v;
    if (tid == 63) g_rowptr[NN] = sm[63];
}

__global__ void scan3_kernel() {
    int i = blockIdx.x * blockDim.x + threadIdx.x;
    if (i < NN) g_rowptr[i] += g_boff[i >> 10];
}

// ---------------- scatter into CSR (edges + self loops) --------------------
__global__ void scatter_kernel(const int* __restrict__ ei) {
    int i = blockIdx.x * blockDim.x + threadIdx.x;
    if (i < EE) {
        int s = ei[i];
        int d = ei[EE + i];
        int pos = g_rowptr[d] + atomicAdd(&g_cursor[d], 1);
        g_esrc[pos] = s;
    } else if (i < ET) {
        int n = i - EE;
        int pos = g_rowptr[n] + atomicAdd(&g_cursor[n], 1);
        g_esrc[pos] = n;
    }
}

// ====================== bf16 mma.sync GEMM + fused dots ====================
// C = A @ B with A bf16 (activations), B bf16 hi/lo (weights).
// 2 accumulating MMAs per product: A*Bh + A*Bl.
#define KC     32
#define APAD   40

__device__ __forceinline__ void mma16816(float* c, const uint32_t* a, const uint32_t* b) {
    asm volatile(
        "mma.sync.aligned.m16n8k16.row.col.f32.bf16.bf16.f32 "
        "{%0,%1,%2,%3}, {%4,%5,%6,%7}, {%8,%9}, {%0,%1,%2,%3};"
        : "+f"(c[0]), "+f"(c[1]), "+f"(c[2]), "+f"(c[3])
        : "r"(a[0]), "r"(a[1]), "r"(a[2]), "r"(a[3]), "r"(b[0]), "r"(b[1]));
}

__global__ __launch_bounds__(256) void mma_gemm_kernel(
    const __nv_bfloat16* __restrict__ Ah,
    const __nv_bfloat16* __restrict__ Bth, const __nv_bfloat16* __restrict__ Btl,
    __nv_bfloat16* __restrict__ Cb,
    const float* __restrict__ avs, const float* __restrict__ avd,
    float* __restrict__ asrc_out, float* __restrict__ adst_out,
    int M, int Nn, int K, int H)
{
    __shared__ unsigned short Ahs[128 * APAD];
    __shared__ unsigned short Bhs[128 * APAD];
    __shared__ unsigned short Bls[128 * APAD];
    __shared__ float s_dt[2][128][2];

    int tid = threadIdx.x;
    int wid = tid >> 5, lane = tid & 31;
    int warp_m = wid & 3;
    int warp_n = wid >> 2;
    int g = lane >> 2, tg = lane & 3;
    int rowBase = blockIdx.y * 128;
    int colBase = blockIdx.x * 128;
    int head = blockIdx.x;

    float acc[2][8][4];
#pragma unroll
    for (int mt = 0; mt < 2; mt++)
#pragma unroll
        for (int nt = 0; nt < 8; nt++)
#pragma unroll
            for (int j = 0; j < 4; j++) acc[mt][nt][j] = 0.f;

    for (int k0 = 0; k0 < K; k0 += KC) {
#pragma unroll
        for (int l = 0; l < 4; l++) {
            int idx = tid + l * 256;          // 0..1023
            int row = idx >> 3;
            int q = idx & 7;
            int gr = rowBase + row;
            uint2 vh = make_uint2(0u, 0u);
            if (gr < M)
                vh = *reinterpret_cast<const uint2*>(&Ah[(size_t)gr * K + k0 + q * 4]);
            *reinterpret_cast<uint2*>(&Ahs[row * APAD + q * 4]) = vh;
        }
#pragma unroll
        for (int l = 0; l < 4; l++) {
            int idx = tid + l * 256;
            int n = idx >> 3;
            int q = idx & 7;
            uint2 vh = *reinterpret_cast<const uint2*>(&Bth[(size_t)(colBase + n) * K + k0 + q * 4]);
            uint2 vl = *reinterpret_cast<const uint2*>(&Btl[(size_t)(colBase + n) * K + k0 + q * 4]);
            *reinterpret_cast<uint2*>(&Bhs[n * APAD + q * 4]) = vh;
            *reinterpret_cast<uint2*>(&Bls[n * APAD + q * 4]) = vl;
        }
        __syncthreads();

#pragma unroll
        for (int ks = 0; ks < 2; ks++) {
            int kk = ks * 16;
            uint32_t afh[2][4];
#pragma unroll
            for (int mt = 0; mt < 2; mt++) {
                int r0 = (warp_m * 32 + mt * 16 + g) * APAD + kk + tg * 2;
                int r8 = r0 + 8 * APAD;
                afh[mt][0] = *reinterpret_cast<uint32_t*>(&Ahs[r0]);
                afh[mt][1] = *reinterpret_cast<uint32_t*>(&Ahs[r8]);
                afh[mt][2] = *reinterpret_cast<uint32_t*>(&Ahs[r0 + 8]);
                afh[mt][3] = *reinterpret_cast<uint32_t*>(&Ahs[r8 + 8]);
            }
#pragma unroll
            for (int nt = 0; nt < 8; nt++) {
                int nb = (warp_n * 64 + nt * 8 + g) * APAD + kk + tg * 2;
                uint32_t bfh[2], bfl[2];
                bfh[0] = *reinterpret_cast<uint32_t*>(&Bhs[nb]);
                bfh[1] = *reinterpret_cast<uint32_t*>(&Bhs[nb + 8]);
                bfl[0] = *reinterpret_cast<uint32_t*>(&Bls[nb]);
                bfl[1] = *reinterpret_cast<uint32_t*>(&Bls[nb + 8]);
#pragma unroll
                for (int mt = 0; mt < 2; mt++) {
                    mma16816(acc[mt][nt], afh[mt], bfh);
                    mma16816(acc[mt][nt], afh[mt], bfl);
                }
            }
        }
        __syncthreads();
    }

    // ---- epilogue: bf16 store + fused attention dots ----
    float ps[2][2] = {{0.f, 0.f}, {0.f, 0.f}};
    float pd[2][2] = {{0.f, 0.f}, {0.f, 0.f}};
#pragma unroll
    for (int nt = 0; nt < 8; nt++) {
        int c0 = colBase + warp_n * 64 + nt * 8 + tg * 2;
        float as0 = avs[c0], as1 = avs[c0 + 1];
        float ad0 = avd[c0], ad1 = avd[c0 + 1];
#pragma unroll
        for (int mt = 0; mt < 2; mt++) {
            int r0 = rowBase + warp_m * 32 + mt * 16 + g;
            __nv_bfloat162 v01 = __floats2bfloat162_rn(acc[mt][nt][0], acc[mt][nt][1]);
            __nv_bfloat162 v23 = __floats2bfloat162_rn(acc[mt][nt][2], acc[mt][nt][3]);
            if (r0 < M)
                *reinterpret_cast<__nv_bfloat162*>(&Cb[(size_t)r0 * Nn + c0]) = v01;
            if (r0 + 8 < M)
                *reinterpret_cast<__nv_bfloat162*>(&Cb[(size_t)(r0 + 8) * Nn + c0]) = v23;
            ps[mt][0] += acc[mt][nt][0] * as0 + acc[mt][nt][1] * as1;
            pd[mt][0] += acc[mt][nt][0] * ad0 + acc[mt][nt][1] * ad1;
            ps[mt][1] += acc[mt][nt][2] * as0 + acc[mt][nt][3] * as1;
            pd[mt][1] += acc[mt][nt][2] * ad0 + acc[mt][nt][3] * ad1;
        }
    }
#pragma unroll
    for (int mt = 0; mt < 2; mt++)
#pragma unroll
        for (int hf = 0; hf < 2; hf++) {
            ps[mt][hf] += __shfl_xor_sync(0xffffffffu, ps[mt][hf], 1);
            ps[mt][hf] += __shfl_xor_sync(0xffffffffu, ps[mt][hf], 2);
            pd[mt][hf] += __shfl_xor_sync(0xffffffffu, pd[mt][hf], 1);
            pd[mt][hf] += __shfl_xor_sync(0xffffffffu, pd[mt][hf], 2);
        }
    if (tg == 0) {
#pragma unroll
        for (int mt = 0; mt < 2; mt++)
#pragma unroll
            for (int hf = 0; hf < 2; hf++) {
                int lr = warp_m * 32 + mt * 16 + g + hf * 8;
                s_dt[0][lr][warp_n] = ps[mt][hf];
                s_dt[1][lr][warp_n] = pd[mt][hf];
            }
    }
    __syncthreads();
    if (tid < 128) {
        int grow = rowBase + tid;
        if (grow < M) {
            asrc_out[grow * H + head] = s_dt[0][tid][0] + s_dt[0][tid][1];
            adst_out[grow * H + head] = s_dt[1][tid][0] + s_dt[1][tid][1];
        }
    }
}

// ---------------- agg layer 1: H=4, uint4 gather (8 ch/thread) -------------
// qw = t&63 owns channels [qw*8, qw*8+8) (all within head qw>>4);
// eo = t>>6 is edge parity; two halves combined via smem at the end.
__global__ __launch_bounds__(128) void agg1_kernel(
    const __nv_bfloat16* __restrict__ h,
    const float* __restrict__ asrc, const float* __restrict__ adst,
    const float* __restrict__ bias,
    __nv_bfloat16* __restrict__ outh)
{
    const int H = HEADS, CH = 64;
    __shared__ int   s_src[CH];
    __shared__ float s_w[CH * H];
    __shared__ float s_f[H];
    __shared__ float s_den[H];
    __shared__ float s_comb[64][8];

    int node = blockIdx.x, t = threadIdx.x;
    int wid = t >> 5, lane = t & 31;
    int qw = t & 63;            // uint4 index within 1KB row
    int eo = t >> 6;            // edge parity group
    int hh = qw >> 4;           // head owning channels qw*8..qw*8+7
    int beg = g_rowptr[node], end = g_rowptr[node + 1];

    float acc[8];
#pragma unroll
    for (int j = 0; j < 8; j++) acc[j] = 0.f;
    float m = -1e30f, ssum = 0.f;
    float ad = adst[node * H + wid];

    for (int cbeg = beg; cbeg < end; cbeg += CH) {
        int clen = min(CH, end - cbeg);
        {
            float lmax = -1e30f;
            for (int i = lane; i < clen; i += 32) {
                int s = g_esrc[cbeg + i];
                if (wid == 0) s_src[i] = s;
                float l = asrc[s * H + wid] + ad;
                l = l > 0.f ? l : 0.2f * l;
                s_w[i * H + wid] = l;
                lmax = fmaxf(lmax, l);
            }
#pragma unroll
            for (int o = 16; o; o >>= 1)
                lmax = fmaxf(lmax, __shfl_xor_sync(0xffffffffu, lmax, o));
            float newm = fmaxf(m, lmax);
            float f = __expf(m - newm);
            m = newm;
            float lsum = 0.f;
            for (int i = lane; i < clen; i += 32) {
                float w = __expf(s_w[i * H + wid] - m);
                s_w[i * H + wid] = w;
                lsum += w;
            }
#pragma unroll
            for (int o = 16; o; o >>= 1)
                lsum += __shfl_xor_sync(0xffffffffu, lsum, o);
            ssum = ssum * f + lsum;
            if (lane == 0) s_f[wid] = f;
        }
        __syncthreads();
        float f = s_f[hh];
#pragma unroll
        for (int j = 0; j < 8; j++) acc[j] *= f;

        int i = eo;
        for (; i + 2 < clen; i += 4) {
            int s0 = s_src[i], s1 = s_src[i + 2];
            float w0 = s_w[i * H + hh], w1 = s_w[(i + 2) * H + hh];
            uint4 v0 = *reinterpret_cast<const uint4*>(h + (size_t)s0 * C1 + qw * 8);
            uint4 v1 = *reinterpret_cast<const uint4*>(h + (size_t)s1 * C1 + qw * 8);
            float2 a0 = __bfloat1622float2(*reinterpret_cast<__nv_bfloat162*>(&v0.x));
            float2 a1 = __bfloat1622float2(*reinterpret_cast<__nv_bfloat162*>(&v0.y));
            float2 a2 = __bfloat1622float2(*reinterpret_cast<__nv_bfloat162*>(&v0.z));
            float2 a3 = __bfloat1622float2(*reinterpret_cast<__nv_bfloat162*>(&v0.w));
            float2 b0 = __bfloat1622float2(*reinterpret_cast<__nv_bfloat162*>(&v1.x));
            float2 b1 = __bfloat1622float2(*reinterpret_cast<__nv_bfloat162*>(&v1.y));
            float2 b2 = __bfloat1622float2(*reinterpret_cast<__nv_bfloat162*>(&v1.z));
            float2 b3 = __bfloat1622float2(*reinterpret_cast<__nv_bfloat162*>(&v1.w));
            acc[0] += w0 * a0.x + w1 * b0.x;  acc[1] += w0 * a0.y + w1 * b0.y;
            acc[2] += w0 * a1.x + w1 * b1.x;  acc[3] += w0 * a1.y + w1 * b1.y;
            acc[4] += w0 * a2.x + w1 * b2.x;  acc[5] += w0 * a2.y + w1 * b2.y;
            acc[6] += w0 * a3.x + w1 * b3.x;  acc[7] += w0 * a3.y + w1 * b3.y;
        }
        for (; i < clen; i += 2) {
            int s = s_src[i];
            float w = s_w[i * H + hh];
            uint4 v = *reinterpret_cast<const uint4*>(h + (size_t)s * C1 + qw * 8);
            float2 a0 = __bfloat1622float2(*reinterpret_cast<__nv_bfloat162*>(&v.x));
            float2 a1 = __bfloat1622float2(*reinterpret_cast<__nv_bfloat162*>(&v.y));
            float2 a2 = __bfloat1622float2(*reinterpret_cast<__nv_bfloat162*>(&v.z));
            float2 a3 = __bfloat1622float2(*reinterpret_cast<__nv_bfloat162*>(&v.w));
            acc[0] += w * a0.x;  acc[1] += w * a0.y;
            acc[2] += w * a1.x;  acc[3] += w * a1.y;
            acc[4] += w * a2.x;  acc[5] += w * a2.y;
            acc[6] += w * a3.x;  acc[7] += w * a3.y;
        }
        __syncthreads();
    }
    if (lane == 0) s_den[wid] = ssum;
    if (eo == 1) {
#pragma unroll
        for (int j = 0; j < 8; j++) s_comb[qw][j] = acc[j];
    }
    __syncthreads();
    if (eo == 0) {
        float den = s_den[hh];
        int ch = qw * 8;
        __nv_bfloat16 o[8];
#pragma unroll
        for (int j = 0; j < 8; j++) {
            float v = (acc[j] + s_comb[qw][j]) / den + bias[ch + j];
            v = v > 0.f ? v : expm1f(v);
            o[j] = __float2bfloat16_rn(v);
        }
        *reinterpret_cast<uint4*>(&outh[(size_t)node * C1 + ch]) =
            *reinterpret_cast<uint4*>(o);
    }
}

// ---------------- agg layer 2: H=1, uint4 gather + fused mean-pool ---------
// qw = t&15 owns channels [qw*8, qw*8+8); eg = t>>4 is the edge group (8 way).
__global__ __launch_bounds__(128) void agg2_kernel(
    const __nv_bfloat16* __restrict__ h,
    const float* __restrict__ asrc, const float* __restrict__ adst,
    const float* __restrict__ bias, const int* __restrict__ batch)
{
    const int CH = 64;
    __shared__ int   s_src[CH];
    __shared__ float s_w[CH];
    __shared__ float s_fd[2];       // [0]=f, [1]=den
    __shared__ float s_comb[8][16][8];

    int node = blockIdx.x, t = threadIdx.x;
    int wid = t >> 5, lane = t & 31;
    int qw = t & 15;
    int eg = t >> 4;                // edge group 0..7
    int beg = g_rowptr[node], end = g_rowptr[node + 1];

    float acc[8];
#pragma unroll
    for (int j = 0; j < 8; j++) acc[j] = 0.f;
    float m = -1e30f, ssum = 0.f;
    float ad = adst[node];

    for (int cbeg = beg; cbeg < end; cbeg += CH) {
        int clen = min(CH, end - cbeg);
        if (wid == 0) {
            float lmax = -1e30f;
            for (int i = lane; i < clen; i += 32) {
                int s = g_esrc[cbeg + i];
                s_src[i] = s;
                float l = asrc[s] + ad;
                l = l > 0.f ? l : 0.2f * l;
                s_w[i] = l;
                lmax = fmaxf(lmax, l);
            }
#pragma unroll
            for (int o = 16; o; o >>= 1)
                lmax = fmaxf(lmax, __shfl_xor_sync(0xffffffffu, lmax, o));
            float newm = fmaxf(m, lmax);
            float f = __expf(m - newm);
            m = newm;
            float lsum = 0.f;
            for (int i = lane; i < clen; i += 32) {
                float w = __expf(s_w[i] - m);
                s_w[i] = w;
                lsum += w;
            }
#pragma unroll
            for (int o = 16; o; o >>= 1)
                lsum += __shfl_xor_sync(0xffffffffu, lsum, o);
            ssum = ssum * f + lsum;
            if (lane == 0) { s_fd[0] = f; s_fd[1] = ssum; }
        }
        __syncthreads();
        float f = s_fd[0];
#pragma unroll
        for (int j = 0; j < 8; j++) acc[j] *= f;

        for (int i = eg; i < clen; i += 8) {
            int s = s_src[i];
            float w = s_w[i];
            uint4 v = *reinterpret_cast<const uint4*>(h + (size_t)s * HIDC + qw * 8);
            float2 a0 = __bfloat1622float2(*reinterpret_cast<__nv_bfloat162*>(&v.x));
            float2 a1 = __bfloat1622float2(*reinterpret_cast<__nv_bfloat162*>(&v.y));
            float2 a2 = __bfloat1622float2(*reinterpret_cast<__nv_bfloat162*>(&v.z));
            float2 a3 = __bfloat1622float2(*reinterpret_cast<__nv_bfloat162*>(&v.w));
            acc[0] += w * a0.x;  acc[1] += w * a0.y;
            acc[2] += w * a1.x;  acc[3] += w * a1.y;
            acc[4] += w * a2.x;  acc[5] += w * a2.y;
            acc[6] += w * a3.x;  acc[7] += w * a3.y;
        }
        __syncthreads();
    }
#pragma unroll
    for (int j = 0; j < 8; j++) s_comb[eg][qw][j] = acc[j];
    __syncthreads();
    int g = batch[node];
    {
        float den = s_fd[1];
        float sum = 0.f;
#pragma unroll
        for (int gq = 0; gq < 8; gq++) sum += s_comb[gq][t >> 3][t & 7];
        float v = sum / den + bias[t];
        v = v > 0.f ? v : expm1f(v);
        atomicAdd(&g_pool[g * HIDC + t], v);
    }
    if (t == 0) atomicAdd(&g_cnt[g], 1.0f);
}

// ---------------- final linear head ----------------------------------------
__global__ void final_kernel(const float* __restrict__ Wl,
                             const float* __restrict__ bl,
                             float* __restrict__ out)
{
    __shared__ float s_red[4];
    int g = blockIdx.x, t = threadIdx.x;
    int lane = t & 31, w = t >> 5;
    float c = fmaxf(g_cnt[g], 1.0f);
    float v = g_pool[g * HIDC + t] / c * Wl[t];
#pragma unroll
    for (int o = 16; o; o >>= 1) v += __shfl_down_sync(0xffffffffu, v, o);
    if (lane == 0) s_red[w] = v;
    __syncthreads();
    if (t == 0) out[g] = s_red[0] + s_red[1] + s_red[2] + s_red[3] + bl[0];
}

// ---------------- launch ----------------------------------------------------
extern "C" void kernel_launch(void* const* d_in, const int* in_sizes, int n_in,
                              void* d_out, int out_size)
{
    const float* x       = (const float*)d_in[0];
    const int*   ei      = (const int*)  d_in[1];
    const int*   batch   = (const int*)  d_in[2];
    const float* W1      = (const float*)d_in[3];
    const float* a_src1  = (const float*)d_in[4];
    const float* a_dst1  = (const float*)d_in[5];
    const float* b1      = (const float*)d_in[6];
    const float* W2      = (const float*)d_in[7];
    const float* a_src2  = (const float*)d_in[8];
    const float* a_dst2  = (const float*)d_in[9];
    const float* b2      = (const float*)d_in[10];
    const float* Wl      = (const float*)d_in[11];
    const float* bl      = (const float*)d_in[12];
    float* out = (float*)d_out;

    float *p_asrc1, *p_adst1, *p_asrc2, *p_adst2;
    __nv_bfloat16 *p_h1b, *p_h2b, *p_xh, *p_a1h, *p_w1h, *p_w1l, *p_w2h, *p_w2l;
    cudaGetSymbolAddress((void**)&p_h1b,   g_h1b);
    cudaGetSymbolAddress((void**)&p_h2b,   g_h2b);
    cudaGetSymbolAddress((void**)&p_asrc1, g_asrc1);
    cudaGetSymbolAddress((void**)&p_adst1, g_adst1);
    cudaGetSymbolAddress((void**)&p_asrc2, g_asrc2);
    cudaGetSymbolAddress((void**)&p_adst2, g_adst2);
    cudaGetSymbolAddress((void**)&p_xh,  g_xh);
    cudaGetSymbolAddress((void**)&p_a1h, g_a1h);
    cudaGetSymbolAddress((void**)&p_w1h, g_w1h);
    cudaGetSymbolAddress((void**)&p_w1l, g_w1l);
    cudaGetSymbolAddress((void**)&p_w2h, g_w2h);
    cudaGetSymbolAddress((void**)&p_w2l, g_w2l);

    const int NBLK = (NN + 1023) / 1024;  // 49

    prep_kernel<<<1024, 256>>>(x, W1, W2);
    count_kernel<<<(EE + 255) / 256, 256>>>(ei);
    scan1_kernel<<<NBLK, 1024>>>();
    scan2_kernel<<<1, 64>>>(NBLK);
    scan3_kernel<<<(NN + 255) / 256, 256>>>();
    scatter_kernel<<<(ET + 255) / 256, 256>>>(ei);

    // layer 1: h1 = x @ W1 (+ fused dots)
    {
        dim3 grid(C1 / 128, (NN + 127) / 128);
        mma_gemm_kernel<<<grid, 256>>>(p_xh, p_w1h, p_w1l, p_h1b,
                                       a_src1, a_dst1, p_asrc1, p_adst1,
                                       NN, C1, FIN, HEADS);
    }
    agg1_kernel<<<NN, 128>>>(p_h1b, p_asrc1, p_adst1, b1, p_a1h);

    // layer 2: h2 = act1 @ W2 (+ fused dots)
    {
        dim3 grid(HIDC / 128, (NN + 127) / 128);
        mma_gemm_kernel<<<grid, 256>>>(p_a1h, p_w2h, p_w2l, p_h2b,
                                       a_src2, a_dst2, p_asrc2, p_adst2,
                                       NN, HIDC, C1, 1);
    }
    // layer 2 agg + fused mean-pool
    agg2_kernel<<<NN, 128>>>(p_h2b, p_asrc2, p_adst2, b2, batch);

    final_kernel<<<GG, HIDC>>>(Wl, bl, out);
}